// round 5
// baseline (speedup 1.0000x reference)
#include <cuda_runtime.h>
#include <cuda_bf16.h>
#include <math.h>
#include <stdint.h>

// Problem constants: B=16, L=S=1024, H=8, E=64, d=512
#define LSEQ 1024
#define LF   513
#define NBH  128            // B*H
#define ATTN_SMEM (3*64*66*sizeof(float2) + 16*64*sizeof(float))

// -------- scratch (device globals; no allocation allowed) --------
__device__ float  g_y  [16777216];           // conv output [B*L][1024]  (67MB)
__device__ float  g_Wt2[1024 * 1536];        // W as [o][t*512+i] (6MB)
__device__ float2 g_qf[(size_t)NBH * LF * 64];
__device__ float2 g_kf[(size_t)NBH * LF * 64];
__device__ float2 g_vf[(size_t)NBH * LF * 64];
__device__ float2 g_of[(size_t)NBH * LF * 64];

// ==================== helpers (base-target PTX only: ldmatrix + mma.sync) ====================
__device__ __forceinline__ uint32_t smem_u32(const void* p) {
    uint32_t a;
    asm("{ .reg .u64 t; cvta.to.shared.u64 t, %1; cvt.u32.u64 %0, t; }" : "=r"(a) : "l"(p));
    return a;
}
__device__ __forceinline__ void ldsm4(uint32_t* r, uint32_t addr) {
    asm volatile("ldmatrix.sync.aligned.m8n8.x4.shared.b16 {%0,%1,%2,%3}, [%4];"
                 : "=r"(r[0]), "=r"(r[1]), "=r"(r[2]), "=r"(r[3]) : "r"(addr));
}
__device__ __forceinline__ void mma_bf16(float* c, const uint32_t* a, uint32_t b0, uint32_t b1) {
    asm volatile("mma.sync.aligned.m16n8k16.row.col.f32.bf16.bf16.f32 "
                 "{%0,%1,%2,%3}, {%4,%5,%6,%7}, {%8,%9}, {%0,%1,%2,%3};"
                 : "+f"(c[0]), "+f"(c[1]), "+f"(c[2]), "+f"(c[3])
                 : "r"(a[0]), "r"(a[1]), "r"(a[2]), "r"(a[3]), "r"(b0), "r"(b1));
}

// =============== W permute: W[o][i][t] -> Wt2[o][t*512+i] ===============
__global__ void k_transpose_w(const float* __restrict__ W) {
    int idx = blockIdx.x * blockDim.x + threadIdx.x;
    if (idx >= 1024 * 512 * 3) return;
    int o = idx / 1536;
    int r = idx - o * 1536;
    int i = r / 3;
    int t = r - i * 3;
    g_Wt2[(size_t)o * 1536 + t * 512 + i] = W[idx];
}

// =============== Conv1d im2col GEMM via mma.sync bf16 (split hi/lo) ===============
// M=16384, N=1024, K=1536. CTA 128x128, K-tile 32, 8 warps (4x2), warp tile 32x64.
// smem stage (40960 B): Ah@0, Al@10240, Bh@20480, Bl@30720; row stride 80 B (40 bf16).
#define CONV_SMEM (2 * 40960)

__device__ __forceinline__ void split4(char* hi, float4 v) {
    __nv_bfloat16 h0 = __float2bfloat16_rn(v.x);
    __nv_bfloat16 h1 = __float2bfloat16_rn(v.y);
    __nv_bfloat16 h2 = __float2bfloat16_rn(v.z);
    __nv_bfloat16 h3 = __float2bfloat16_rn(v.w);
    __nv_bfloat162 hp0 = {h0, h1}, hp1 = {h2, h3};
    *(uint2*)hi = make_uint2(*(uint32_t*)&hp0, *(uint32_t*)&hp1);
    __nv_bfloat162 lp0 = __floats2bfloat162_rn(v.x - __bfloat162float(h0),
                                               v.y - __bfloat162float(h1));
    __nv_bfloat162 lp1 = __floats2bfloat162_rn(v.z - __bfloat162float(h2),
                                               v.w - __bfloat162float(h3));
    *(uint2*)(hi + 10240) = make_uint2(*(uint32_t*)&lp0, *(uint32_t*)&lp1);
}

__global__ void __launch_bounds__(256, 1)
k_conv_mma(const float* __restrict__ x, const float* __restrict__ bias) {
    extern __shared__ char smem[];
    const uint32_t sb = smem_u32(smem);
    const int tid = threadIdx.x, lane = tid & 31, wid = tid >> 5;
    const int m0 = blockIdx.y * 128, n0 = blockIdx.x * 128;
    const int warp_m = (wid & 3) * 32, warp_n = (wid >> 2) * 64;

    // ldmatrix per-lane addressing
    const int rA = (lane & 7) + (lane & 8);          // A row within 16
    const int kA = ((lane >> 4) & 1) * 8;            // A k-half
    const int nB = (lane & 7) + ((lane >> 4) & 1) * 8;  // B n within 16
    const int kB = ((lane >> 3) & 1) * 8;            // B k-half

    float c[2][8][4];
#pragma unroll
    for (int mt = 0; mt < 2; mt++)
#pragma unroll
        for (int nt = 0; nt < 8; nt++)
#pragma unroll
            for (int r = 0; r < 4; r++) c[mt][nt][r] = 0.f;

    float4 aR[4], bR[4];

    auto gload = [&](int kt) {
        const int tap = kt >> 4;                // (kt*32)/512
        const int kbase = (kt * 32) & 511;
#pragma unroll
        for (int r = 0; r < 4; r++) {
            const int idx = tid + r * 256;
            const int row = idx >> 3, c4 = (idx & 7) * 4;
            const int m = m0 + row, bb = m >> 10, l = m & 1023;
            const int lp = l + tap - 1;
            aR[r] = make_float4(0.f, 0.f, 0.f, 0.f);
            if (lp >= 0 && lp < 1024)
                aR[r] = *(const float4*)(x + ((size_t)bb * 1024 + lp) * 512 + kbase + c4);
            bR[r] = *(const float4*)(g_Wt2 + (size_t)(n0 + row) * 1536 + kt * 32 + c4);
        }
    };
    auto sstore = [&](int buf) {
        char* base = smem + buf * 40960;
#pragma unroll
        for (int r = 0; r < 4; r++) {
            const int idx = tid + r * 256;
            const int row = idx >> 3, c4 = (idx & 7) * 4;
            split4(base + row * 80 + c4 * 2, aR[r]);
            split4(base + 20480 + row * 80 + c4 * 2, bR[r]);
        }
    };

    gload(0);
    sstore(0);
    __syncthreads();

    for (int kt = 0; kt < 48; kt++) {
        if (kt < 47) gload(kt + 1);

        const uint32_t sbase = sb + (kt & 1) * 40960;
#pragma unroll
        for (int ks = 0; ks < 2; ks++) {
            uint32_t ah[2][4], al[2][4];
#pragma unroll
            for (int mt = 0; mt < 2; mt++) {
                const uint32_t aaddr = sbase + (warp_m + mt * 16 + rA) * 80 + (ks * 16 + kA) * 2;
                ldsm4(ah[mt], aaddr);
                ldsm4(al[mt], aaddr + 10240);
            }
            uint32_t bh[4][4], bl[4][4];
#pragma unroll
            for (int np = 0; np < 4; np++) {
                const uint32_t baddr = sbase + 20480 + (warp_n + np * 16 + nB) * 80 + (ks * 16 + kB) * 2;
                ldsm4(bh[np], baddr);
                ldsm4(bl[np], baddr + 10240);
            }
#pragma unroll
            for (int mt = 0; mt < 2; mt++)
#pragma unroll
                for (int np = 0; np < 4; np++)
#pragma unroll
                    for (int half = 0; half < 2; half++) {
                        float* cc = c[mt][np * 2 + half];
                        const uint32_t bh0 = bh[np][half * 2], bh1 = bh[np][half * 2 + 1];
                        const uint32_t bl0 = bl[np][half * 2], bl1 = bl[np][half * 2 + 1];
                        mma_bf16(cc, ah[mt], bh0, bh1);
                        mma_bf16(cc, ah[mt], bl0, bl1);
                        mma_bf16(cc, al[mt], bh0, bh1);
                    }
        }
        __syncthreads();
        if (kt < 47) sstore((kt + 1) & 1);
        __syncthreads();
    }

    // epilogue: add bias, write g_y
#pragma unroll
    for (int mt = 0; mt < 2; mt++) {
        const int row0 = m0 + warp_m + mt * 16 + (lane >> 2);
#pragma unroll
        for (int nt = 0; nt < 8; nt++) {
            const int col = n0 + warp_n + nt * 8 + (lane & 3) * 2;
            const float2 bv = *(const float2*)(bias + col);
            *(float2*)(g_y + (size_t)row0 * 1024 + col) =
                make_float2(c[mt][nt][0] + bv.x, c[mt][nt][1] + bv.y);
            *(float2*)(g_y + (size_t)(row0 + 8) * 1024 + col) =
                make_float2(c[mt][nt][2] + bv.x, c[mt][nt][3] + bv.y);
        }
    }
}

// =============== 1024-pt Stockham radix-2 FFT in shared memory ===============
__device__ __forceinline__ void fft1024_sm(float2* s0, float2* s1, int tid, float sign) {
    float2* src = s0;
    float2* dst = s1;
    int n = 1024;
    int logstr = 0;
#pragma unroll
    for (int st = 0; st < 10; st++) {
        const int m = n >> 1;
        const int str = 1 << logstr;
#pragma unroll
        for (int r = 0; r < 2; r++) {
            const int i = tid + r * 256;
            const int p = i >> logstr;
            const int q = i & (str - 1);
            const float2 a = src[q + str * p];
            const float2 b = src[q + str * (p + m)];
            const float2 su = make_float2(a.x + b.x, a.y + b.y);
            const float2 di = make_float2(a.x - b.x, a.y - b.y);
            const float ang = sign * 2.0f * (float)p / (float)n;  // units of pi
            float sw, cw;
            sincospif(ang, &sw, &cw);
            dst[q + str * (2 * p)]     = su;
            dst[q + str * (2 * p + 1)] = make_float2(di.x * cw - di.y * sw,
                                                     di.x * sw + di.y * cw);
        }
        __syncthreads();
        float2* tp = src; src = dst; dst = tp;
        n >>= 1;
        logstr++;
    }
}

// =============== forward rFFT (ortho) ===============
__global__ __launch_bounds__(256) void k_fft_fwd(const float* __restrict__ in, int mode) {
    __shared__ float2 s0[1024];
    __shared__ float2 s1[1024];
    const int seq = blockIdx.x;              // b*512 + c,  c = h*64+e
    const int b = seq >> 9, c = seq & 511;
    const int tid = threadIdx.x;
    for (int l = tid; l < 1024; l += 256) {
        float v;
        if (mode == 0) {
            const float* yr = g_y + ((size_t)(b * 1024 + l)) * 1024;
            const float a = yr[c];
            const float g = yr[c + 512];
            v = a * (1.0f / (1.0f + __expf(-g)));   // GLU
        } else {
            v = in[((size_t)(b * 1024 + l)) * 512 + c];
        }
        s0[l] = make_float2(v, 0.f);
    }
    __syncthreads();
    fft1024_sm(s0, s1, tid, -1.0f);
    float2* outp = (mode == 0) ? g_qf : (mode == 1 ? g_kf : g_vf);
    const int bh = b * 8 + (c >> 6), e = c & 63;
    float2* o = outp + (size_t)bh * LF * 64 + e;
    const float sc = 1.0f / 32.0f;           // ortho: 1/sqrt(1024)
    for (int xx = tid; xx < LF; xx += 256) {
        const float2 t = s0[xx];
        o[(size_t)xx * 64] = make_float2(t.x * sc, t.y * sc);
    }
}

// =============== fused frequency-domain flash attention ===============
__global__ __launch_bounds__(256) void k_attn() {
    extern __shared__ float2 sm[];
    float2 (*Qs)[66] = (float2(*)[66])sm;                 // [e][x]
    float2 (*KP)[66] = (float2(*)[66])(sm + 64 * 66);     // K:[e][y] then P:[y][x]
    float2 (*Vs)[66] = (float2(*)[66])(sm + 2 * 64 * 66); // [y][e]
    float* dpart = (float*)(sm + 3 * 64 * 66);            // [16][64]

    const int bh = blockIdx.x;
    const int x0 = blockIdx.y * 64;
    const int tid = threadIdx.x;
    const int tx = tid & 15, ty = tid >> 4;

    const float2* Qg = g_qf + (size_t)bh * LF * 64;
    const float2* Kg = g_kf + (size_t)bh * LF * 64;
    const float2* Vg = g_vf + (size_t)bh * LF * 64;

#pragma unroll
    for (int r = 0; r < 16; r++) {
        const int idx = tid + r * 256;
        const int xl = idx >> 6, e = idx & 63;
        float2 v = make_float2(0.f, 0.f);
        if (x0 + xl < LF) v = Qg[(size_t)(x0 + xl) * 64 + e];
        Qs[e][xl] = v;
    }

    float oar[4][4], oai[4][4];
#pragma unroll
    for (int i = 0; i < 4; i++)
#pragma unroll
        for (int j = 0; j < 4; j++) { oar[i][j] = 0.f; oai[i][j] = 0.f; }
    float dloc[4] = {0.f, 0.f, 0.f, 0.f};
    __syncthreads();

    for (int y0 = 0; y0 < LF; y0 += 64) {
#pragma unroll
        for (int r = 0; r < 16; r++) {
            const int idx = tid + r * 256;
            const int yl = idx >> 6, e = idx & 63;
            float2 kv = make_float2(0.f, 0.f), vv = make_float2(0.f, 0.f);
            if (y0 + yl < LF) {
                kv = Kg[(size_t)(y0 + yl) * 64 + e];
                vv = Vg[(size_t)(y0 + yl) * 64 + e];
            }
            KP[e][yl] = kv;
            Vs[yl][e] = vv;
        }
        __syncthreads();

        float sr[4][4], si[4][4];
#pragma unroll
        for (int i = 0; i < 4; i++)
#pragma unroll
            for (int j = 0; j < 4; j++) { sr[i][j] = 0.f; si[i][j] = 0.f; }

#pragma unroll 8
        for (int e = 0; e < 64; e++) {
            float2 qa[4], kb[4];
#pragma unroll
            for (int i = 0; i < 4; i++) qa[i] = Qs[e][tx * 4 + i];
#pragma unroll
            for (int j = 0; j < 4; j++) kb[j] = KP[e][ty * 4 + j];
#pragma unroll
            for (int i = 0; i < 4; i++)
#pragma unroll
                for (int j = 0; j < 4; j++) {
                    sr[i][j] = fmaf(qa[i].x, kb[j].x, fmaf(qa[i].y, kb[j].y, sr[i][j]));
                    si[i][j] = fmaf(qa[i].y, kb[j].x, fmaf(-qa[i].x, kb[j].y, si[i][j]));
                }
        }
        __syncthreads();

#pragma unroll
        for (int i = 0; i < 4; i++)
#pragma unroll
            for (int j = 0; j < 4; j++) {
                const float re = sr[i][j] * 0.125f;
                const float im = si[i][j] * 0.125f;
                const float mag = __fsqrt_rn(re * re + im * im);
                const float w = 1.0f + 1.0f / (1.0f + __expf(-mag));
                dloc[i] += mag * w;
                KP[ty * 4 + j][tx * 4 + i] = make_float2(re * w, im * w);
            }
        __syncthreads();

#pragma unroll 8
        for (int y = 0; y < 64; y++) {
            float2 pa[4], vb[4];
#pragma unroll
            for (int i = 0; i < 4; i++) pa[i] = KP[y][tx * 4 + i];
#pragma unroll
            for (int j = 0; j < 4; j++) vb[j] = Vs[y][ty * 4 + j];
#pragma unroll
            for (int i = 0; i < 4; i++)
#pragma unroll
                for (int j = 0; j < 4; j++) {
                    oar[i][j] = fmaf(pa[i].x, vb[j].x, fmaf(-pa[i].y, vb[j].y, oar[i][j]));
                    oai[i][j] = fmaf(pa[i].x, vb[j].y, fmaf(pa[i].y, vb[j].x, oai[i][j]));
                }
        }
        __syncthreads();
    }

#pragma unroll
    for (int i = 0; i < 4; i++) dpart[ty * 64 + tx * 4 + i] = dloc[i];
    __syncthreads();

    float2* Og = g_of + (size_t)bh * LF * 64;
#pragma unroll
    for (int i = 0; i < 4; i++) {
        const int xl = tx * 4 + i;
        const int xg = x0 + xl;
        if (xg >= LF) continue;
        float dn = 0.f;
#pragma unroll
        for (int t = 0; t < 16; t++) dn += dpart[t * 64 + xl];
        const float inv = 1.0f / fmaxf(dn, 1e-12f);
#pragma unroll
        for (int j = 0; j < 4; j++)
            Og[(size_t)xg * 64 + ty * 4 + j] =
                make_float2(oar[i][j] * inv, oai[i][j] * inv);
    }
}

// =============== inverse: Hermitian extension + iFFT (ortho) ===============
__global__ __launch_bounds__(256) void k_fft_inv(float* __restrict__ out) {
    __shared__ float2 s0[1024];
    __shared__ float2 s1[1024];
    const int seq = blockIdx.x;             // bh*64 + e
    const int bh = seq >> 6, e = seq & 63;
    const float2* ip = g_of + (size_t)bh * LF * 64 + e;
    const int tid = threadIdx.x;
    for (int xx = tid; xx < 1024; xx += 256) {
        float2 v;
        if (xx <= 512) {
            v = ip[(size_t)xx * 64];
        } else {
            const float2 t = ip[(size_t)(1024 - xx) * 64];
            v = make_float2(t.x, -t.y);
        }
        s0[xx] = v;
    }
    __syncthreads();
    fft1024_sm(s0, s1, tid, +1.0f);
    const int b = bh >> 3, h = bh & 7;
    float* op = out + (size_t)b * 1024 * 512 + h * 64 + e;
    const float sc = 1.0f / 32.0f;
    for (int l = tid; l < 1024; l += 256) op[(size_t)l * 512] = s0[l].x * sc;
}

// ============================ launch ============================
extern "C" void kernel_launch(void* const* d_in, const int* in_sizes, int n_in,
                              void* d_out, int out_size) {
    const float* q    = (const float*)d_in[0];
    const float* k    = (const float*)d_in[1];
    const float* v    = (const float*)d_in[2];
    const float* W    = (const float*)d_in[3];
    const float* bias = (const float*)d_in[4];
    float* out = (float*)d_out;

    cudaFuncSetAttribute(k_attn, cudaFuncAttributeMaxDynamicSharedMemorySize,
                         (int)ATTN_SMEM);
    cudaFuncSetAttribute(k_conv_mma, cudaFuncAttributeMaxDynamicSharedMemorySize,
                         (int)CONV_SMEM);

    k_transpose_w<<<(1024 * 512 * 3 + 255) / 256, 256>>>(W);
    k_conv_mma<<<dim3(8, 128), 256, CONV_SMEM>>>(q, bias);
    k_fft_fwd<<<8192, 256>>>(nullptr, 0);   // q2 (GLU of conv output)
    k_fft_fwd<<<8192, 256>>>(k, 1);
    k_fft_fwd<<<8192, 256>>>(v, 2);
    k_attn<<<dim3(128, 9), 256, ATTN_SMEM>>>();
    k_fft_inv<<<8192, 256>>>(out);
}

// round 10
// speedup vs baseline: 2.1467x; 2.1467x over previous
#include <cuda_runtime.h>
#include <cuda_bf16.h>
#include <math.h>
#include <stdint.h>

// Problem constants: B=16, L=S=1024, H=8, E=64, d=512
#define LSEQ 1024
#define LF   513
#define NBH  128            // B*H

// -------- scratch (device globals; no allocation allowed) --------
__device__ __align__(256) float  g_y  [16777216];     // conv output [B*L][1024]
__device__ __align__(256) float  g_Wt2[1024 * 1536];  // W as [o][t*512+i]
__device__ __align__(256) float2 g_of[(size_t)NBH * LF * 64];
// bf16 split planes for attention (MMA-native layouts, zero-padded)
__device__ __align__(256) __nv_bfloat16 g_qsp_h[(size_t)NBH * 128 * 640];
__device__ __align__(256) __nv_bfloat16 g_qsp_l[(size_t)NBH * 128 * 640];
__device__ __align__(256) __nv_bfloat16 g_ksp_h[(size_t)NBH * 128 * 576];
__device__ __align__(256) __nv_bfloat16 g_ksp_l[(size_t)NBH * 128 * 576];
__device__ __align__(256) __nv_bfloat16 g_vsp_h[(size_t)NBH * 64 * 1152];
__device__ __align__(256) __nv_bfloat16 g_vsp_l[(size_t)NBH * 64 * 1152];

// ==================== helpers (base-target PTX only) ====================
__device__ __forceinline__ uint32_t smem_u32(const void* p) {
    uint32_t a;
    asm("{ .reg .u64 t; cvta.to.shared.u64 t, %1; cvt.u32.u64 %0, t; }" : "=r"(a) : "l"(p));
    return a;
}
__device__ __forceinline__ void ldsm4(uint32_t* r, uint32_t addr) {
    asm volatile("ldmatrix.sync.aligned.m8n8.x4.shared.b16 {%0,%1,%2,%3}, [%4];"
                 : "=r"(r[0]), "=r"(r[1]), "=r"(r[2]), "=r"(r[3]) : "r"(addr));
}
__device__ __forceinline__ void ldsm4t(uint32_t* r, uint32_t addr) {
    asm volatile("ldmatrix.sync.aligned.m8n8.x4.trans.shared.b16 {%0,%1,%2,%3}, [%4];"
                 : "=r"(r[0]), "=r"(r[1]), "=r"(r[2]), "=r"(r[3]) : "r"(addr));
}
__device__ __forceinline__ void mma_bf16(float* c, const uint32_t* a, uint32_t b0, uint32_t b1) {
    asm volatile("mma.sync.aligned.m16n8k16.row.col.f32.bf16.bf16.f32 "
                 "{%0,%1,%2,%3}, {%4,%5,%6,%7}, {%8,%9}, {%0,%1,%2,%3};"
                 : "+f"(c[0]), "+f"(c[1]), "+f"(c[2]), "+f"(c[3])
                 : "r"(a[0]), "r"(a[1]), "r"(a[2]), "r"(a[3]), "r"(b0), "r"(b1));
}
#define CP16(dst, src) asm volatile("cp.async.cg.shared.global [%0], [%1], 16;" :: "r"(dst), "l"(src))
#define CP_COMMIT()    asm volatile("cp.async.commit_group;" ::: "memory")
#define CP_WAIT0()     asm volatile("cp.async.wait_group 0;" ::: "memory")
#define SGN2 0x80008000u

// =============== W permute: W[o][i][t] -> Wt2[o][t*512+i] ===============
__global__ void k_transpose_w(const float* __restrict__ W) {
    int idx = blockIdx.x * blockDim.x + threadIdx.x;
    if (idx >= 1024 * 512 * 3) return;
    int o = idx / 1536;
    int r = idx - o * 1536;
    int i = r / 3;
    int t = r - i * 3;
    g_Wt2[(size_t)o * 1536 + t * 512 + i] = W[idx];
}

// =============== Conv1d im2col GEMM via mma.sync bf16 (split hi/lo) ===============
#define CONV_SMEM (2 * 40960)

__device__ __forceinline__ void split4(char* hi, float4 v) {
    __nv_bfloat16 h0 = __float2bfloat16_rn(v.x);
    __nv_bfloat16 h1 = __float2bfloat16_rn(v.y);
    __nv_bfloat16 h2 = __float2bfloat16_rn(v.z);
    __nv_bfloat16 h3 = __float2bfloat16_rn(v.w);
    __nv_bfloat162 hp0 = {h0, h1}, hp1 = {h2, h3};
    *(uint2*)hi = make_uint2(*(uint32_t*)&hp0, *(uint32_t*)&hp1);
    __nv_bfloat162 lp0 = __floats2bfloat162_rn(v.x - __bfloat162float(h0),
                                               v.y - __bfloat162float(h1));
    __nv_bfloat162 lp1 = __floats2bfloat162_rn(v.z - __bfloat162float(h2),
                                               v.w - __bfloat162float(h3));
    *(uint2*)(hi + 10240) = make_uint2(*(uint32_t*)&lp0, *(uint32_t*)&lp1);
}

__global__ void __launch_bounds__(256, 1)
k_conv_mma(const float* __restrict__ x, const float* __restrict__ bias) {
    extern __shared__ char smem[];
    const uint32_t sb = smem_u32(smem);
    const int tid = threadIdx.x, lane = tid & 31, wid = tid >> 5;
    const int m0 = blockIdx.y * 128, n0 = blockIdx.x * 128;
    const int warp_m = (wid & 3) * 32, warp_n = (wid >> 2) * 64;

    const int rA = (lane & 7) + (lane & 8);
    const int kA = ((lane >> 4) & 1) * 8;
    const int nB = (lane & 7) + ((lane >> 4) & 1) * 8;
    const int kB = ((lane >> 3) & 1) * 8;

    float c[2][8][4];
#pragma unroll
    for (int mt = 0; mt < 2; mt++)
#pragma unroll
        for (int nt = 0; nt < 8; nt++)
#pragma unroll
            for (int r = 0; r < 4; r++) c[mt][nt][r] = 0.f;

    float4 aR[4], bR[4];

    auto gload = [&](int kt) {
        const int tap = kt >> 4;
        const int kbase = (kt * 32) & 511;
#pragma unroll
        for (int r = 0; r < 4; r++) {
            const int idx = tid + r * 256;
            const int row = idx >> 3, c4 = (idx & 7) * 4;
            const int m = m0 + row, bb = m >> 10, l = m & 1023;
            const int lp = l + tap - 1;
            aR[r] = make_float4(0.f, 0.f, 0.f, 0.f);
            if (lp >= 0 && lp < 1024)
                aR[r] = *(const float4*)(x + ((size_t)bb * 1024 + lp) * 512 + kbase + c4);
            bR[r] = *(const float4*)(g_Wt2 + (size_t)(n0 + row) * 1536 + kt * 32 + c4);
        }
    };
    auto sstore = [&](int buf) {
        char* base = smem + buf * 40960;
#pragma unroll
        for (int r = 0; r < 4; r++) {
            const int idx = tid + r * 256;
            const int row = idx >> 3, c4 = (idx & 7) * 4;
            split4(base + row * 80 + c4 * 2, aR[r]);
            split4(base + 20480 + row * 80 + c4 * 2, bR[r]);
        }
    };

    gload(0);
    sstore(0);
    __syncthreads();

    for (int kt = 0; kt < 48; kt++) {
        if (kt < 47) gload(kt + 1);

        const uint32_t sbase = sb + (kt & 1) * 40960;
#pragma unroll
        for (int ks = 0; ks < 2; ks++) {
            uint32_t ah[2][4], al[2][4];
#pragma unroll
            for (int mt = 0; mt < 2; mt++) {
                const uint32_t aaddr = sbase + (warp_m + mt * 16 + rA) * 80 + (ks * 16 + kA) * 2;
                ldsm4(ah[mt], aaddr);
                ldsm4(al[mt], aaddr + 10240);
            }
            uint32_t bh[4][4], bl[4][4];
#pragma unroll
            for (int np = 0; np < 4; np++) {
                const uint32_t baddr = sbase + 20480 + (warp_n + np * 16 + nB) * 80 + (ks * 16 + kB) * 2;
                ldsm4(bh[np], baddr);
                ldsm4(bl[np], baddr + 10240);
            }
#pragma unroll
            for (int mt = 0; mt < 2; mt++)
#pragma unroll
                for (int np = 0; np < 4; np++)
#pragma unroll
                    for (int half = 0; half < 2; half++) {
                        float* cc = c[mt][np * 2 + half];
                        const uint32_t bh0 = bh[np][half * 2], bh1 = bh[np][half * 2 + 1];
                        const uint32_t bl0 = bl[np][half * 2], bl1 = bl[np][half * 2 + 1];
                        mma_bf16(cc, ah[mt], bh0, bh1);
                        mma_bf16(cc, ah[mt], bl0, bl1);
                        mma_bf16(cc, al[mt], bh0, bh1);
                    }
        }
        __syncthreads();
        if (kt < 47) sstore((kt + 1) & 1);
        __syncthreads();
    }

#pragma unroll
    for (int mt = 0; mt < 2; mt++) {
        const int row0 = m0 + warp_m + mt * 16 + (lane >> 2);
#pragma unroll
        for (int nt = 0; nt < 8; nt++) {
            const int col = n0 + warp_n + nt * 8 + (lane & 3) * 2;
            const float2 bv = *(const float2*)(bias + col);
            *(float2*)(g_y + (size_t)row0 * 1024 + col) =
                make_float2(c[mt][nt][0] + bv.x, c[mt][nt][1] + bv.y);
            *(float2*)(g_y + (size_t)(row0 + 8) * 1024 + col) =
                make_float2(c[mt][nt][2] + bv.x, c[mt][nt][3] + bv.y);
        }
    }
}

// =============== 1024-pt Stockham radix-2 FFT in shared memory ===============
__device__ __forceinline__ void fft1024_sm(float2* s0, float2* s1, int tid, float sign) {
    float2* src = s0;
    float2* dst = s1;
    int n = 1024;
    int logstr = 0;
#pragma unroll
    for (int st = 0; st < 10; st++) {
        const int m = n >> 1;
        const int str = 1 << logstr;
#pragma unroll
        for (int r = 0; r < 2; r++) {
            const int i = tid + r * 256;
            const int p = i >> logstr;
            const int q = i & (str - 1);
            const float2 a = src[q + str * p];
            const float2 b = src[q + str * (p + m)];
            const float2 su = make_float2(a.x + b.x, a.y + b.y);
            const float2 di = make_float2(a.x - b.x, a.y - b.y);
            const float ang = sign * 2.0f * (float)p / (float)n;
            float sw, cw;
            sincospif(ang, &sw, &cw);
            dst[q + str * (2 * p)]     = su;
            dst[q + str * (2 * p + 1)] = make_float2(di.x * cw - di.y * sw,
                                                     di.x * sw + di.y * cw);
        }
        __syncthreads();
        float2* tp = src; src = dst; dst = tp;
        n >>= 1;
        logstr++;
    }
}

__device__ __forceinline__ void split1(float v, __nv_bfloat16& h, __nv_bfloat16& l) {
    h = __float2bfloat16_rn(v);
    l = __float2bfloat16_rn(v - __bfloat162float(h));
}

// =============== forward rFFT (ortho) -> bf16 split planes ===============
// mode 0: q2=GLU(conv) -> g_qsp [bh][plane*64+e][640]
// mode 1: k            -> g_ksp [bh][plane*64+e][576]
// mode 2: v            -> g_vsp [bh][e][Vr 576 | Vi 576]
__global__ __launch_bounds__(256) void k_fft_fwd(const float* __restrict__ in, int mode) {
    __shared__ float2 s0[1024];
    __shared__ float2 s1[1024];
    const int seq = blockIdx.x;              // b*512 + c,  c = h*64+e
    const int b = seq >> 9, c = seq & 511;
    const int tid = threadIdx.x;
    for (int l = tid; l < 1024; l += 256) {
        float v;
        if (mode == 0) {
            const float* yr = g_y + ((size_t)(b * 1024 + l)) * 1024;
            const float a = yr[c];
            const float g = yr[c + 512];
            v = a * (1.0f / (1.0f + __expf(-g)));
        } else {
            v = in[((size_t)(b * 1024 + l)) * 512 + c];
        }
        s0[l] = make_float2(v, 0.f);
    }
    __syncthreads();
    fft1024_sm(s0, s1, tid, -1.0f);
    const int bh = b * 8 + (c >> 6), e = c & 63;
    const float sc = 1.0f / 32.0f;
    if (mode == 2) {
        __nv_bfloat16* vh = g_vsp_h + ((size_t)(bh * 64 + e)) * 1152;
        __nv_bfloat16* vl = g_vsp_l + ((size_t)(bh * 64 + e)) * 1152;
        for (int xx = tid; xx < 576; xx += 256) {
            float re = 0.f, im = 0.f;
            if (xx < LF) { re = s0[xx].x * sc; im = s0[xx].y * sc; }
            __nv_bfloat16 h, l;
            split1(re, h, l); vh[xx] = h; vl[xx] = l;
            split1(im, h, l); vh[576 + xx] = h; vl[576 + xx] = l;
        }
    } else {
        const int width = (mode == 0) ? 640 : 576;
        __nv_bfloat16* base_h = (mode == 0) ? g_qsp_h : g_ksp_h;
        __nv_bfloat16* base_l = (mode == 0) ? g_qsp_l : g_ksp_l;
        __nv_bfloat16* rh = base_h + ((size_t)(bh * 128 + e)) * width;
        __nv_bfloat16* rl = base_l + ((size_t)(bh * 128 + e)) * width;
        __nv_bfloat16* ih = base_h + ((size_t)(bh * 128 + 64 + e)) * width;
        __nv_bfloat16* il = base_l + ((size_t)(bh * 128 + 64 + e)) * width;
        for (int xx = tid; xx < width; xx += 256) {
            float re = 0.f, im = 0.f;
            if (xx < LF) { re = s0[xx].x * sc; im = s0[xx].y * sc; }
            __nv_bfloat16 h, l;
            split1(re, h, l); rh[xx] = h; rl[xx] = l;
            split1(im, h, l); ih[xx] = h; il[xx] = l;
        }
    }
}

// =============== frequency-domain attention on mma.sync (split bf16) ===============
// Per block: (bh, x-tile of 128). y-loop of 9 tiles x 64.
// smem: Q[k128][x128]s272 h/l, K[k128][y64]s144 h/l, V[e64][k128]s272 h/l,
//       P[x128][k128]s272 h/l, dpart[128][8] f32
#define AQH 0
#define AQL 34816
#define AKH 69632
#define AKL 88064
#define AVH 106496
#define AVL 123904
#define APH 141312
#define APL 176128
#define ADP 210944
#define ATTN_SMEM2 215040

__global__ void __launch_bounds__(256, 1) k_attn_mma() {
    extern __shared__ char smc[];
    const uint32_t sb = smem_u32(smc);
    const int tid = threadIdx.x, lane = tid & 31, wid = tid >> 5;
    const int bh = blockIdx.x, x0 = blockIdx.y * 128;
    const int wm = (wid & 3) * 32, wn = (wid >> 2) * 32, nwidx = wid >> 2;

    // trans-A (Q): row k, col m
    const int kTa = (lane & 7) + ((lane >> 4) & 1) * 8;
    const int mTa = ((lane >> 3) & 1) * 8;
    // trans-B (K): row k, col n
    const int kTb = (lane & 7) + ((lane >> 3) & 1) * 8;
    const int nTb = ((lane >> 4) & 1) * 8;
    // non-trans A (P)
    const int rA = (lane & 7) + (lane & 8);
    const int kA = ((lane >> 4) & 1) * 8;
    // non-trans B (V)
    const int nB = (lane & 7) + ((lane >> 4) & 1) * 8;
    const int kB = ((lane >> 3) & 1) * 8;

    float sr[2][4][4], si_[2][4][4], orr[2][4][4], oii[2][4][4];
#pragma unroll
    for (int mt = 0; mt < 2; mt++)
#pragma unroll
        for (int t = 0; t < 4; t++)
#pragma unroll
            for (int r = 0; r < 4; r++) { orr[mt][t][r] = 0.f; oii[mt][t][r] = 0.f; }
    float dloc[2][2] = {{0.f, 0.f}, {0.f, 0.f}};

    // --- Q tile cp.async: 128 rows x 256B, hi+lo (128*16 = 2048 chunk slots) ---
#pragma unroll
    for (int i = 0; i < 8; i++) {
        const int cc = tid + i * 256;
        const int row = cc >> 4, off = (cc & 15) * 16;
        const char* sh = (const char*)(g_qsp_h + ((size_t)(bh * 128 + row)) * 640 + x0) + off;
        const char* sl = (const char*)(g_qsp_l + ((size_t)(bh * 128 + row)) * 640 + x0) + off;
        CP16(sb + AQH + row * 272 + off, sh);
        CP16(sb + AQL + row * 272 + off, sl);
    }
    CP_COMMIT();

    for (int yt = 0; yt < 9; yt++) {
        // K tile: 128 rows x 128B; V tile: 64 rows x 2 segs x 128B
#pragma unroll
        for (int i = 0; i < 4; i++) {
            const int cc = tid + i * 256;
            const int row = cc >> 3, off = (cc & 7) * 16;
            const char* sh = (const char*)(g_ksp_h + ((size_t)(bh * 128 + row)) * 576 + yt * 64) + off;
            const char* sl = (const char*)(g_ksp_l + ((size_t)(bh * 128 + row)) * 576 + yt * 64) + off;
            CP16(sb + AKH + row * 144 + off, sh);
            CP16(sb + AKL + row * 144 + off, sl);
        }
#pragma unroll
        for (int i = 0; i < 4; i++) {
            const int cc = tid + i * 256;
            const int row = cc >> 4, seg = (cc >> 3) & 1, off = (cc & 7) * 16;
            const char* sh = (const char*)(g_vsp_h + ((size_t)(bh * 64 + row)) * 1152 + seg * 576 + yt * 64) + off;
            const char* sl = (const char*)(g_vsp_l + ((size_t)(bh * 64 + row)) * 1152 + seg * 576 + yt * 64) + off;
            CP16(sb + AVH + row * 272 + seg * 128 + off, sh);
            CP16(sb + AVL + row * 272 + seg * 128 + off, sl);
        }
        CP_COMMIT();
        CP_WAIT0();
        __syncthreads();

#pragma unroll
        for (int mt = 0; mt < 2; mt++)
#pragma unroll
            for (int t = 0; t < 4; t++)
#pragma unroll
                for (int r = 0; r < 4; r++) { sr[mt][t][r] = 0.f; si_[mt][t][r] = 0.f; }

        // ---- S = Qf conj(Kf)^T : chunk pairs (c0 = real-plane, c1 = imag-plane) ----
        for (int p = 0; p < 4; p++) {
            const int c0 = p * 16, c1 = c0 + 64;
            uint32_t a0h[2][4], a0l[2][4], a1h[2][4], a1l[2][4];
#pragma unroll
            for (int mt = 0; mt < 2; mt++) {
                const uint32_t col = (wm + mt * 16 + mTa) * 2;
                uint32_t ad = sb + AQH + (c0 + kTa) * 272 + col;
                ldsm4t(a0h[mt], ad); ldsm4t(a0l[mt], ad + (AQL - AQH));
                ad = sb + AQH + (c1 + kTa) * 272 + col;
                ldsm4t(a1h[mt], ad); ldsm4t(a1l[mt], ad + (AQL - AQH));
            }
            uint32_t b0h[2][4], b0l[2][4], b1h[2][4], b1l[2][4];
#pragma unroll
            for (int np = 0; np < 2; np++) {
                const uint32_t col = (wn + np * 16 + nTb) * 2;
                uint32_t ad = sb + AKH + (c0 + kTb) * 144 + col;
                ldsm4t(b0h[np], ad); ldsm4t(b0l[np], ad + (AKL - AKH));
                ad = sb + AKH + (c1 + kTb) * 144 + col;
                ldsm4t(b1h[np], ad); ldsm4t(b1l[np], ad + (AKL - AKH));
            }
#pragma unroll
            for (int mt = 0; mt < 2; mt++)
#pragma unroll
                for (int np = 0; np < 2; np++)
#pragma unroll
                    for (int hf = 0; hf < 2; hf++) {
                        float* R = sr[mt][np * 2 + hf];
                        float* I = si_[mt][np * 2 + hf];
                        const uint32_t h0a = b0h[np][hf * 2], h0b = b0h[np][hf * 2 + 1];
                        const uint32_t l0a = b0l[np][hf * 2], l0b = b0l[np][hf * 2 + 1];
                        const uint32_t h1a = b1h[np][hf * 2], h1b = b1h[np][hf * 2 + 1];
                        const uint32_t l1a = b1l[np][hf * 2], l1b = b1l[np][hf * 2 + 1];
                        const uint32_t nh1a = h1a ^ SGN2, nh1b = h1b ^ SGN2;
                        const uint32_t nl1a = l1a ^ SGN2, nl1b = l1b ^ SGN2;
                        // sr = Qr*Kr + Qi*Ki
                        mma_bf16(R, a0h[mt], h0a, h0b);
                        mma_bf16(R, a0h[mt], l0a, l0b);
                        mma_bf16(R, a0l[mt], h0a, h0b);
                        mma_bf16(R, a1h[mt], h1a, h1b);
                        mma_bf16(R, a1h[mt], l1a, l1b);
                        mma_bf16(R, a1l[mt], h1a, h1b);
                        // si = Qi*Kr - Qr*Ki
                        mma_bf16(I, a1h[mt], h0a, h0b);
                        mma_bf16(I, a1h[mt], l0a, l0b);
                        mma_bf16(I, a1l[mt], h0a, h0b);
                        mma_bf16(I, a0h[mt], nh1a, nh1b);
                        mma_bf16(I, a0h[mt], nl1a, nl1b);
                        mma_bf16(I, a0l[mt], nh1a, nh1b);
                    }
        }

        // ---- magnitude gate -> P (split bf16 into smem), accumulate denom ----
#pragma unroll
        for (int mt = 0; mt < 2; mt++)
#pragma unroll
            for (int np = 0; np < 2; np++)
#pragma unroll
                for (int hf = 0; hf < 2; hf++) {
                    float* R = sr[mt][np * 2 + hf];
                    float* I = si_[mt][np * 2 + hf];
                    const int ycol = wn + np * 16 + hf * 8 + (lane & 3) * 2;
#pragma unroll
                    for (int jh = 0; jh < 2; jh++) {
                        const int row = wm + mt * 16 + (lane >> 2) + jh * 8;
                        const float re0 = R[jh * 2] * 0.125f, im0 = I[jh * 2] * 0.125f;
                        const float re1 = R[jh * 2 + 1] * 0.125f, im1 = I[jh * 2 + 1] * 0.125f;
                        const float m0 = __fsqrt_rn(re0 * re0 + im0 * im0);
                        const float m1 = __fsqrt_rn(re1 * re1 + im1 * im1);
                        const float w0 = 1.0f + 1.0f / (1.0f + __expf(-m0));
                        const float w1 = 1.0f + 1.0f / (1.0f + __expf(-m1));
                        dloc[mt][jh] += m0 * w0 + m1 * w1;
                        const float pr0 = re0 * w0, pr1 = re1 * w1;
                        const float pi0 = im0 * w0, pi1 = im1 * w1;
                        __nv_bfloat16 h0, l0, h1, l1;
                        split1(pr0, h0, l0); split1(pr1, h1, l1);
                        __nv_bfloat162 hp = {h0, h1}, lp = {l0, l1};
                        *(uint32_t*)(smc + APH + row * 272 + ycol * 2) = *(uint32_t*)&hp;
                        *(uint32_t*)(smc + APL + row * 272 + ycol * 2) = *(uint32_t*)&lp;
                        split1(pi0, h0, l0); split1(pi1, h1, l1);
                        __nv_bfloat162 hp2 = {h0, h1}, lp2 = {l0, l1};
                        *(uint32_t*)(smc + APH + row * 272 + 128 + ycol * 2) = *(uint32_t*)&hp2;
                        *(uint32_t*)(smc + APL + row * 272 + 128 + ycol * 2) = *(uint32_t*)&lp2;
                    }
                }
        __syncthreads();

        // ---- O += P @ Vf : A = P [x][Pr|Pi], B = V [e][Vr|Vi] ----
        for (int p = 0; p < 4; p++) {
            const int c0 = p * 16, c1 = c0 + 64;
            uint32_t a0h[2][4], a0l[2][4], a1h[2][4], a1l[2][4];
#pragma unroll
            for (int mt = 0; mt < 2; mt++) {
                const uint32_t rowb = sb + APH + (wm + mt * 16 + rA) * 272;
                uint32_t ad = rowb + (c0 + kA) * 2;
                ldsm4(a0h[mt], ad); ldsm4(a0l[mt], ad + (APL - APH));
                ad = rowb + (c1 + kA) * 2;
                ldsm4(a1h[mt], ad); ldsm4(a1l[mt], ad + (APL - APH));
            }
            uint32_t b0h[2][4], b0l[2][4], b1h[2][4], b1l[2][4];
#pragma unroll
            for (int np = 0; np < 2; np++) {
                const uint32_t rowb = sb + AVH + (wn + np * 16 + nB) * 272;
                uint32_t ad = rowb + (c0 + kB) * 2;
                ldsm4(b0h[np], ad); ldsm4(b0l[np], ad + (AVL - AVH));
                ad = rowb + (c1 + kB) * 2;
                ldsm4(b1h[np], ad); ldsm4(b1l[np], ad + (AVL - AVH));
            }
#pragma unroll
            for (int mt = 0; mt < 2; mt++)
#pragma unroll
                for (int np = 0; np < 2; np++)
#pragma unroll
                    for (int hf = 0; hf < 2; hf++) {
                        float* Or = orr[mt][np * 2 + hf];
                        float* Oi = oii[mt][np * 2 + hf];
                        const uint32_t h0a = b0h[np][hf * 2], h0b = b0h[np][hf * 2 + 1];
                        const uint32_t l0a = b0l[np][hf * 2], l0b = b0l[np][hf * 2 + 1];
                        const uint32_t h1a = b1h[np][hf * 2], h1b = b1h[np][hf * 2 + 1];
                        const uint32_t l1a = b1l[np][hf * 2], l1b = b1l[np][hf * 2 + 1];
                        const uint32_t nh1a = h1a ^ SGN2, nh1b = h1b ^ SGN2;
                        const uint32_t nl1a = l1a ^ SGN2, nl1b = l1b ^ SGN2;
                        // or = Pr*Vr - Pi*Vi
                        mma_bf16(Or, a0h[mt], h0a, h0b);
                        mma_bf16(Or, a0h[mt], l0a, l0b);
                        mma_bf16(Or, a0l[mt], h0a, h0b);
                        mma_bf16(Or, a1h[mt], nh1a, nh1b);
                        mma_bf16(Or, a1h[mt], nl1a, nl1b);
                        mma_bf16(Or, a1l[mt], nh1a, nh1b);
                        // oi = Pr*Vi + Pi*Vr
                        mma_bf16(Oi, a0h[mt], h1a, h1b);
                        mma_bf16(Oi, a0h[mt], l1a, l1b);
                        mma_bf16(Oi, a0l[mt], h1a, h1b);
                        mma_bf16(Oi, a1h[mt], h0a, h0b);
                        mma_bf16(Oi, a1h[mt], l0a, l0b);
                        mma_bf16(Oi, a1l[mt], h0a, h0b);
                    }
        }
        __syncthreads();
    }

    // ---- denominator reduce (deterministic slots) ----
    float* dp = (float*)(smc + ADP);
#pragma unroll
    for (int mt = 0; mt < 2; mt++)
#pragma unroll
        for (int jh = 0; jh < 2; jh++) {
            const int row = wm + mt * 16 + (lane >> 2) + jh * 8;
            dp[row * 8 + nwidx * 4 + (lane & 3)] = dloc[mt][jh];
        }
    __syncthreads();

#pragma unroll
    for (int mt = 0; mt < 2; mt++)
#pragma unroll
        for (int jh = 0; jh < 2; jh++) {
            const int row = wm + mt * 16 + (lane >> 2) + jh * 8;
            const int x = x0 + row;
            if (x >= LF) continue;
            float dn = 0.f;
#pragma unroll
            for (int t = 0; t < 8; t++) dn += dp[row * 8 + t];
            const float inv = 1.0f / fmaxf(dn, 1e-12f);
#pragma unroll
            for (int np = 0; np < 2; np++)
#pragma unroll
                for (int hf = 0; hf < 2; hf++) {
                    const int e0 = wn + np * 16 + hf * 8 + (lane & 3) * 2;
                    const float* Or = orr[mt][np * 2 + hf];
                    const float* Oi = oii[mt][np * 2 + hf];
                    const int j0 = jh * 2, j1 = jh * 2 + 1;
                    float4 v = make_float4(Or[j0] * inv, Oi[j0] * inv,
                                           Or[j1] * inv, Oi[j1] * inv);
                    *(float4*)(g_of + ((size_t)(bh * LF + x)) * 64 + e0) = v;
                }
        }
}

// =============== inverse: Hermitian extension + iFFT (ortho) ===============
__global__ __launch_bounds__(256) void k_fft_inv(float* __restrict__ out) {
    __shared__ float2 s0[1024];
    __shared__ float2 s1[1024];
    const int seq = blockIdx.x;             // bh*64 + e
    const int bh = seq >> 6, e = seq & 63;
    const float2* ip = g_of + (size_t)bh * LF * 64 + e;
    const int tid = threadIdx.x;
    for (int xx = tid; xx < 1024; xx += 256) {
        float2 v;
        if (xx <= 512) {
            v = ip[(size_t)xx * 64];
        } else {
            const float2 t = ip[(size_t)(1024 - xx) * 64];
            v = make_float2(t.x, -t.y);
        }
        s0[xx] = v;
    }
    __syncthreads();
    fft1024_sm(s0, s1, tid, +1.0f);
    const int b = bh >> 3, h = bh & 7;
    float* op = out + (size_t)b * 1024 * 512 + h * 64 + e;
    const float sc = 1.0f / 32.0f;
    for (int l = tid; l < 1024; l += 256) op[(size_t)l * 512] = s0[l].x * sc;
}

// ============================ launch ============================
extern "C" void kernel_launch(void* const* d_in, const int* in_sizes, int n_in,
                              void* d_out, int out_size) {
    const float* q    = (const float*)d_in[0];
    const float* k    = (const float*)d_in[1];
    const float* v    = (const float*)d_in[2];
    const float* W    = (const float*)d_in[3];
    const float* bias = (const float*)d_in[4];
    float* out = (float*)d_out;

    cudaFuncSetAttribute(k_conv_mma, cudaFuncAttributeMaxDynamicSharedMemorySize,
                         (int)CONV_SMEM);
    cudaFuncSetAttribute(k_attn_mma, cudaFuncAttributeMaxDynamicSharedMemorySize,
                         (int)ATTN_SMEM2);

    k_transpose_w<<<(1024 * 512 * 3 + 255) / 256, 256>>>(W);
    k_conv_mma<<<dim3(8, 128), 256, CONV_SMEM>>>(q, bias);
    k_fft_fwd<<<8192, 256>>>(nullptr, 0);   // q2 (GLU of conv output)
    k_fft_fwd<<<8192, 256>>>(k, 1);
    k_fft_fwd<<<8192, 256>>>(v, 2);
    k_attn_mma<<<dim3(128, 5), 256, ATTN_SMEM2>>>();
    k_fft_inv<<<8192, 256>>>(out);
}

// round 13
// speedup vs baseline: 2.2647x; 1.0550x over previous
#include <cuda_runtime.h>
#include <cuda_bf16.h>
#include <math.h>
#include <stdint.h>

// Problem constants: B=16, L=S=1024, H=8, E=64, d=512
#define LSEQ 1024
#define LF   513
#define NBH  128            // B*H

// -------- scratch (device globals; no allocation allowed) --------
__device__ __align__(256) float  g_y  [16777216];     // conv output [B*L][1024]
__device__ __align__(256) float  g_Wt2[1024 * 1536];  // W as [o][t*512+i]
__device__ __align__(256) float2 g_of[(size_t)NBH * LF * 64];
// bf16 split planes for attention (MMA-native layouts, zero-padded)
__device__ __align__(256) __nv_bfloat16 g_qsp_h[(size_t)NBH * 128 * 640];
__device__ __align__(256) __nv_bfloat16 g_qsp_l[(size_t)NBH * 128 * 640];
__device__ __align__(256) __nv_bfloat16 g_ksp_h[(size_t)NBH * 128 * 576];
__device__ __align__(256) __nv_bfloat16 g_ksp_l[(size_t)NBH * 128 * 576];
__device__ __align__(256) __nv_bfloat16 g_vsp_h[(size_t)NBH * 64 * 1152];
__device__ __align__(256) __nv_bfloat16 g_vsp_l[(size_t)NBH * 64 * 1152];

// ==================== helpers (base-target PTX only) ====================
__device__ __forceinline__ uint32_t smem_u32(const void* p) {
    uint32_t a;
    asm("{ .reg .u64 t; cvta.to.shared.u64 t, %1; cvt.u32.u64 %0, t; }" : "=r"(a) : "l"(p));
    return a;
}
__device__ __forceinline__ void ldsm4(uint32_t* r, uint32_t addr) {
    asm volatile("ldmatrix.sync.aligned.m8n8.x4.shared.b16 {%0,%1,%2,%3}, [%4];"
                 : "=r"(r[0]), "=r"(r[1]), "=r"(r[2]), "=r"(r[3]) : "r"(addr));
}
__device__ __forceinline__ void ldsm4t(uint32_t* r, uint32_t addr) {
    asm volatile("ldmatrix.sync.aligned.m8n8.x4.trans.shared.b16 {%0,%1,%2,%3}, [%4];"
                 : "=r"(r[0]), "=r"(r[1]), "=r"(r[2]), "=r"(r[3]) : "r"(addr));
}
__device__ __forceinline__ void mma_bf16(float* c, const uint32_t* a, uint32_t b0, uint32_t b1) {
    asm volatile("mma.sync.aligned.m16n8k16.row.col.f32.bf16.bf16.f32 "
                 "{%0,%1,%2,%3}, {%4,%5,%6,%7}, {%8,%9}, {%0,%1,%2,%3};"
                 : "+f"(c[0]), "+f"(c[1]), "+f"(c[2]), "+f"(c[3])
                 : "r"(a[0]), "r"(a[1]), "r"(a[2]), "r"(a[3]), "r"(b0), "r"(b1));
}
#define CP16(dst, src) asm volatile("cp.async.cg.shared.global [%0], [%1], 16;" :: "r"(dst), "l"(src))
#define CP_COMMIT()    asm volatile("cp.async.commit_group;" ::: "memory")
#define CP_WAIT0()     asm volatile("cp.async.wait_group 0;" ::: "memory")
#define SGN2 0x80008000u

// =============== W permute: W[o][i][t] -> Wt2[o][t*512+i] ===============
__global__ void k_transpose_w(const float* __restrict__ W) {
    int idx = blockIdx.x * blockDim.x + threadIdx.x;
    if (idx >= 1024 * 512 * 3) return;
    int o = idx / 1536;
    int r = idx - o * 1536;
    int i = r / 3;
    int t = r - i * 3;
    g_Wt2[(size_t)o * 1536 + t * 512 + i] = W[idx];
}

// =============== Conv1d im2col GEMM via mma.sync bf16 (split hi/lo) ===============
#define CONV_SMEM (2 * 40960)

__device__ __forceinline__ void split4(char* hi, float4 v) {
    __nv_bfloat16 h0 = __float2bfloat16_rn(v.x);
    __nv_bfloat16 h1 = __float2bfloat16_rn(v.y);
    __nv_bfloat16 h2 = __float2bfloat16_rn(v.z);
    __nv_bfloat16 h3 = __float2bfloat16_rn(v.w);
    __nv_bfloat162 hp0 = {h0, h1}, hp1 = {h2, h3};
    *(uint2*)hi = make_uint2(*(uint32_t*)&hp0, *(uint32_t*)&hp1);
    __nv_bfloat162 lp0 = __floats2bfloat162_rn(v.x - __bfloat162float(h0),
                                               v.y - __bfloat162float(h1));
    __nv_bfloat162 lp1 = __floats2bfloat162_rn(v.z - __bfloat162float(h2),
                                               v.w - __bfloat162float(h3));
    *(uint2*)(hi + 10240) = make_uint2(*(uint32_t*)&lp0, *(uint32_t*)&lp1);
}

__global__ void __launch_bounds__(256, 1)
k_conv_mma(const float* __restrict__ x, const float* __restrict__ bias) {
    extern __shared__ char smem[];
    const uint32_t sb = smem_u32(smem);
    const int tid = threadIdx.x, lane = tid & 31, wid = tid >> 5;
    const int m0 = blockIdx.y * 128, n0 = blockIdx.x * 128;
    const int warp_m = (wid & 3) * 32, warp_n = (wid >> 2) * 64;

    const int rA = (lane & 7) + (lane & 8);
    const int kA = ((lane >> 4) & 1) * 8;
    const int nB = (lane & 7) + ((lane >> 4) & 1) * 8;
    const int kB = ((lane >> 3) & 1) * 8;

    float c[2][8][4];
#pragma unroll
    for (int mt = 0; mt < 2; mt++)
#pragma unroll
        for (int nt = 0; nt < 8; nt++)
#pragma unroll
            for (int r = 0; r < 4; r++) c[mt][nt][r] = 0.f;

    float4 aR[4], bR[4];

    auto gload = [&](int kt) {
        const int tap = kt >> 4;
        const int kbase = (kt * 32) & 511;
#pragma unroll
        for (int r = 0; r < 4; r++) {
            const int idx = tid + r * 256;
            const int row = idx >> 3, c4 = (idx & 7) * 4;
            const int m = m0 + row, bb = m >> 10, l = m & 1023;
            const int lp = l + tap - 1;
            aR[r] = make_float4(0.f, 0.f, 0.f, 0.f);
            if (lp >= 0 && lp < 1024)
                aR[r] = *(const float4*)(x + ((size_t)bb * 1024 + lp) * 512 + kbase + c4);
            bR[r] = *(const float4*)(g_Wt2 + (size_t)(n0 + row) * 1536 + kt * 32 + c4);
        }
    };
    auto sstore = [&](int buf) {
        char* base = smem + buf * 40960;
#pragma unroll
        for (int r = 0; r < 4; r++) {
            const int idx = tid + r * 256;
            const int row = idx >> 3, c4 = (idx & 7) * 4;
            split4(base + row * 80 + c4 * 2, aR[r]);
            split4(base + 20480 + row * 80 + c4 * 2, bR[r]);
        }
    };

    gload(0);
    sstore(0);
    __syncthreads();

    for (int kt = 0; kt < 48; kt++) {
        if (kt < 47) gload(kt + 1);

        const uint32_t sbase = sb + (kt & 1) * 40960;
#pragma unroll
        for (int ks = 0; ks < 2; ks++) {
            uint32_t ah[2][4], al[2][4];
#pragma unroll
            for (int mt = 0; mt < 2; mt++) {
                const uint32_t aaddr = sbase + (warp_m + mt * 16 + rA) * 80 + (ks * 16 + kA) * 2;
                ldsm4(ah[mt], aaddr);
                ldsm4(al[mt], aaddr + 10240);
            }
            uint32_t bh[4][4], bl[4][4];
#pragma unroll
            for (int np = 0; np < 4; np++) {
                const uint32_t baddr = sbase + 20480 + (warp_n + np * 16 + nB) * 80 + (ks * 16 + kB) * 2;
                ldsm4(bh[np], baddr);
                ldsm4(bl[np], baddr + 10240);
            }
#pragma unroll
            for (int mt = 0; mt < 2; mt++)
#pragma unroll
                for (int np = 0; np < 4; np++)
#pragma unroll
                    for (int half = 0; half < 2; half++) {
                        float* cc = c[mt][np * 2 + half];
                        const uint32_t bh0 = bh[np][half * 2], bh1 = bh[np][half * 2 + 1];
                        const uint32_t bl0 = bl[np][half * 2], bl1 = bl[np][half * 2 + 1];
                        mma_bf16(cc, ah[mt], bh0, bh1);
                        mma_bf16(cc, ah[mt], bl0, bl1);
                        mma_bf16(cc, al[mt], bh0, bh1);
                    }
        }
        __syncthreads();
        if (kt < 47) sstore((kt + 1) & 1);
        __syncthreads();
    }

#pragma unroll
    for (int mt = 0; mt < 2; mt++) {
        const int row0 = m0 + warp_m + mt * 16 + (lane >> 2);
#pragma unroll
        for (int nt = 0; nt < 8; nt++) {
            const int col = n0 + warp_n + nt * 8 + (lane & 3) * 2;
            const float2 bv = *(const float2*)(bias + col);
            *(float2*)(g_y + (size_t)row0 * 1024 + col) =
                make_float2(c[mt][nt][0] + bv.x, c[mt][nt][1] + bv.y);
            *(float2*)(g_y + (size_t)(row0 + 8) * 1024 + col) =
                make_float2(c[mt][nt][2] + bv.x, c[mt][nt][3] + bv.y);
        }
    }
}

// =============== 1024-pt radix-4 Stockham FFT in shared memory ===============
// 5 stages, 256 threads, 1 radix-4 butterfly per thread per stage.
// Skewed addressing SKW(i)=i+(i>>5) keeps all stages <=2-way bank conflicts.
// Result ends in s1 (odd number of buffer swaps). Arrays must be 1056 float2.
#define SKW(i) ((i) + ((i) >> 5))

__device__ __forceinline__ float2 cmul(float2 a, float2 b) {
    return make_float2(a.x * b.x - a.y * b.y, a.x * b.y + a.y * b.x);
}

__device__ __forceinline__ void fft1024_r4(float2* s0, float2* s1, int tid, float sign) {
    float2* src = s0;
    float2* dst = s1;
    int n = 1024;
    int logstr = 0;
#pragma unroll
    for (int st = 0; st < 5; st++) {
        const int mq = n >> 2;
        const int str = 1 << logstr;
        const int p = tid >> logstr;
        const int q = tid & (str - 1);
        const int base = q + str * p;
        const int offc = str * mq;
        const float2 x0 = src[SKW(base)];
        const float2 x1 = src[SKW(base + offc)];
        const float2 x2 = src[SKW(base + 2 * offc)];
        const float2 x3 = src[SKW(base + 3 * offc)];
        const float2 a  = make_float2(x0.x + x2.x, x0.y + x2.y);
        const float2 b  = make_float2(x0.x - x2.x, x0.y - x2.y);
        const float2 cc = make_float2(x1.x + x3.x, x1.y + x3.y);
        const float2 dd = make_float2(x1.x - x3.x, x1.y - x3.y);
        const float2 idd = make_float2(-sign * dd.y, sign * dd.x);   // i*sign*(x1-x3)
        float sw, cw;
        sincospif(sign * 2.0f * (float)p / (float)n, &sw, &cw);
        const float2 w1 = make_float2(cw, sw);
        const float2 w2 = cmul(w1, w1);
        const float2 w3 = cmul(w1, w2);
        const int ob = q + str * 4 * p;
        dst[SKW(ob)]           = make_float2(a.x + cc.x, a.y + cc.y);
        dst[SKW(ob + str)]     = cmul(w1, make_float2(b.x + idd.x, b.y + idd.y));
        dst[SKW(ob + str * 2)] = cmul(w2, make_float2(a.x - cc.x, a.y - cc.y));
        dst[SKW(ob + str * 3)] = cmul(w3, make_float2(b.x - idd.x, b.y - idd.y));
        __syncthreads();
        float2* tp = src; src = dst; dst = tp;
        n >>= 2;
        logstr += 2;
    }
}

__device__ __forceinline__ void split1(float v, __nv_bfloat16& h, __nv_bfloat16& l) {
    h = __float2bfloat16_rn(v);
    l = __float2bfloat16_rn(v - __bfloat162float(h));
}

// =============== forward rFFT (ortho) -> bf16 split planes ===============
// mode 0: q2=GLU(conv) -> g_qsp [bh][plane*64+e][640]
// mode 1: k            -> g_ksp [bh][plane*64+e][576]
// mode 2: v            -> g_vsp [bh][e][Vr 576 | Vi 576]
__global__ __launch_bounds__(256) void k_fft_fwd(const float* __restrict__ in, int mode) {
    __shared__ float2 s0[1056];
    __shared__ float2 s1[1056];
    const int seq = blockIdx.x;              // b*512 + c,  c = h*64+e
    const int b = seq >> 9, c = seq & 511;
    const int tid = threadIdx.x;
    for (int l = tid; l < 1024; l += 256) {
        float v;
        if (mode == 0) {
            const float* yr = g_y + ((size_t)(b * 1024 + l)) * 1024;
            const float a = yr[c];
            const float g = yr[c + 512];
            v = a * (1.0f / (1.0f + __expf(-g)));
        } else {
            v = in[((size_t)(b * 1024 + l)) * 512 + c];
        }
        s0[SKW(l)] = make_float2(v, 0.f);
    }
    __syncthreads();
    fft1024_r4(s0, s1, tid, -1.0f);          // result in s1
    const int bh = b * 8 + (c >> 6), e = c & 63;
    const float sc = 1.0f / 32.0f;
    if (mode == 2) {
        __nv_bfloat16* vh = g_vsp_h + ((size_t)(bh * 64 + e)) * 1152;
        __nv_bfloat16* vl = g_vsp_l + ((size_t)(bh * 64 + e)) * 1152;
        for (int xx = tid; xx < 576; xx += 256) {
            float re = 0.f, im = 0.f;
            if (xx < LF) { re = s1[SKW(xx)].x * sc; im = s1[SKW(xx)].y * sc; }
            __nv_bfloat16 h, l;
            split1(re, h, l); vh[xx] = h; vl[xx] = l;
            split1(im, h, l); vh[576 + xx] = h; vl[576 + xx] = l;
        }
    } else {
        const int width = (mode == 0) ? 640 : 576;
        __nv_bfloat16* base_h = (mode == 0) ? g_qsp_h : g_ksp_h;
        __nv_bfloat16* base_l = (mode == 0) ? g_qsp_l : g_ksp_l;
        __nv_bfloat16* rh = base_h + ((size_t)(bh * 128 + e)) * width;
        __nv_bfloat16* rl = base_l + ((size_t)(bh * 128 + e)) * width;
        __nv_bfloat16* ih = base_h + ((size_t)(bh * 128 + 64 + e)) * width;
        __nv_bfloat16* il = base_l + ((size_t)(bh * 128 + 64 + e)) * width;
        for (int xx = tid; xx < width; xx += 256) {
            float re = 0.f, im = 0.f;
            if (xx < LF) { re = s1[SKW(xx)].x * sc; im = s1[SKW(xx)].y * sc; }
            __nv_bfloat16 h, l;
            split1(re, h, l); rh[xx] = h; rl[xx] = l;
            split1(im, h, l); ih[xx] = h; il[xx] = l;
        }
    }
}

// =============== frequency-domain attention on mma.sync (split bf16) ===============
// Per block: (bh, x-tile of 128). y-loop of 9 tiles x 64.
// smem: Q[k128][x128]s272 h/l, K[k128][y64]s144 h/l, V[e64][k128]s272 h/l,
//       P[x128][k128]s272 h/l, dpart[128][8] f32
#define AQH 0
#define AQL 34816
#define AKH 69632
#define AKL 88064
#define AVH 106496
#define AVL 123904
#define APH 141312
#define APL 176128
#define ADP 210944
#define ATTN_SMEM2 215040

__global__ void __launch_bounds__(256, 1) k_attn_mma() {
    extern __shared__ char smc[];
    const uint32_t sb = smem_u32(smc);
    const int tid = threadIdx.x, lane = tid & 31, wid = tid >> 5;
    const int bh = blockIdx.x, x0 = blockIdx.y * 128;
    const int wm = (wid & 3) * 32, wn = (wid >> 2) * 32, nwidx = wid >> 2;

    // trans-A (Q): row k, col m
    const int kTa = (lane & 7) + ((lane >> 4) & 1) * 8;
    const int mTa = ((lane >> 3) & 1) * 8;
    // trans-B (K): row k, col n
    const int kTb = (lane & 7) + ((lane >> 3) & 1) * 8;
    const int nTb = ((lane >> 4) & 1) * 8;
    // non-trans A (P)
    const int rA = (lane & 7) + (lane & 8);
    const int kA = ((lane >> 4) & 1) * 8;
    // non-trans B (V)
    const int nB = (lane & 7) + ((lane >> 4) & 1) * 8;
    const int kB = ((lane >> 3) & 1) * 8;

    float sr[2][4][4], si_[2][4][4], orr[2][4][4], oii[2][4][4];
#pragma unroll
    for (int mt = 0; mt < 2; mt++)
#pragma unroll
        for (int t = 0; t < 4; t++)
#pragma unroll
            for (int r = 0; r < 4; r++) { orr[mt][t][r] = 0.f; oii[mt][t][r] = 0.f; }
    float dloc[2][2] = {{0.f, 0.f}, {0.f, 0.f}};

    // --- Q tile cp.async: 128 rows x 256B, hi+lo (128*16 = 2048 chunk slots) ---
#pragma unroll
    for (int i = 0; i < 8; i++) {
        const int cc = tid + i * 256;
        const int row = cc >> 4, off = (cc & 15) * 16;
        const char* sh = (const char*)(g_qsp_h + ((size_t)(bh * 128 + row)) * 640 + x0) + off;
        const char* sl = (const char*)(g_qsp_l + ((size_t)(bh * 128 + row)) * 640 + x0) + off;
        CP16(sb + AQH + row * 272 + off, sh);
        CP16(sb + AQL + row * 272 + off, sl);
    }
    CP_COMMIT();

    for (int yt = 0; yt < 9; yt++) {
        // K tile: 128 rows x 128B; V tile: 64 rows x 2 segs x 128B
#pragma unroll
        for (int i = 0; i < 4; i++) {
            const int cc = tid + i * 256;
            const int row = cc >> 3, off = (cc & 7) * 16;
            const char* sh = (const char*)(g_ksp_h + ((size_t)(bh * 128 + row)) * 576 + yt * 64) + off;
            const char* sl = (const char*)(g_ksp_l + ((size_t)(bh * 128 + row)) * 576 + yt * 64) + off;
            CP16(sb + AKH + row * 144 + off, sh);
            CP16(sb + AKL + row * 144 + off, sl);
        }
#pragma unroll
        for (int i = 0; i < 4; i++) {
            const int cc = tid + i * 256;
            const int row = cc >> 4, seg = (cc >> 3) & 1, off = (cc & 7) * 16;
            const char* sh = (const char*)(g_vsp_h + ((size_t)(bh * 64 + row)) * 1152 + seg * 576 + yt * 64) + off;
            const char* sl = (const char*)(g_vsp_l + ((size_t)(bh * 64 + row)) * 1152 + seg * 576 + yt * 64) + off;
            CP16(sb + AVH + row * 272 + seg * 128 + off, sh);
            CP16(sb + AVL + row * 272 + seg * 128 + off, sl);
        }
        CP_COMMIT();
        CP_WAIT0();
        __syncthreads();

#pragma unroll
        for (int mt = 0; mt < 2; mt++)
#pragma unroll
            for (int t = 0; t < 4; t++)
#pragma unroll
                for (int r = 0; r < 4; r++) { sr[mt][t][r] = 0.f; si_[mt][t][r] = 0.f; }

        // ---- S = Qf conj(Kf)^T : chunk pairs (c0 = real-plane, c1 = imag-plane) ----
        for (int p = 0; p < 4; p++) {
            const int c0 = p * 16, c1 = c0 + 64;
            uint32_t a0h[2][4], a0l[2][4], a1h[2][4], a1l[2][4];
#pragma unroll
            for (int mt = 0; mt < 2; mt++) {
                const uint32_t col = (wm + mt * 16 + mTa) * 2;
                uint32_t ad = sb + AQH + (c0 + kTa) * 272 + col;
                ldsm4t(a0h[mt], ad); ldsm4t(a0l[mt], ad + (AQL - AQH));
                ad = sb + AQH + (c1 + kTa) * 272 + col;
                ldsm4t(a1h[mt], ad); ldsm4t(a1l[mt], ad + (AQL - AQH));
            }
            uint32_t b0h[2][4], b0l[2][4], b1h[2][4], b1l[2][4];
#pragma unroll
            for (int np = 0; np < 2; np++) {
                const uint32_t col = (wn + np * 16 + nTb) * 2;
                uint32_t ad = sb + AKH + (c0 + kTb) * 144 + col;
                ldsm4t(b0h[np], ad); ldsm4t(b0l[np], ad + (AKL - AKH));
                ad = sb + AKH + (c1 + kTb) * 144 + col;
                ldsm4t(b1h[np], ad); ldsm4t(b1l[np], ad + (AKL - AKH));
            }
#pragma unroll
            for (int mt = 0; mt < 2; mt++)
#pragma unroll
                for (int np = 0; np < 2; np++)
#pragma unroll
                    for (int hf = 0; hf < 2; hf++) {
                        float* R = sr[mt][np * 2 + hf];
                        float* I = si_[mt][np * 2 + hf];
                        const uint32_t h0a = b0h[np][hf * 2], h0b = b0h[np][hf * 2 + 1];
                        const uint32_t l0a = b0l[np][hf * 2], l0b = b0l[np][hf * 2 + 1];
                        const uint32_t h1a = b1h[np][hf * 2], h1b = b1h[np][hf * 2 + 1];
                        const uint32_t l1a = b1l[np][hf * 2], l1b = b1l[np][hf * 2 + 1];
                        const uint32_t nh1a = h1a ^ SGN2, nh1b = h1b ^ SGN2;
                        const uint32_t nl1a = l1a ^ SGN2, nl1b = l1b ^ SGN2;
                        // sr = Qr*Kr + Qi*Ki
                        mma_bf16(R, a0h[mt], h0a, h0b);
                        mma_bf16(R, a0h[mt], l0a, l0b);
                        mma_bf16(R, a0l[mt], h0a, h0b);
                        mma_bf16(R, a1h[mt], h1a, h1b);
                        mma_bf16(R, a1h[mt], l1a, l1b);
                        mma_bf16(R, a1l[mt], h1a, h1b);
                        // si = Qi*Kr - Qr*Ki
                        mma_bf16(I, a1h[mt], h0a, h0b);
                        mma_bf16(I, a1h[mt], l0a, l0b);
                        mma_bf16(I, a1l[mt], h0a, h0b);
                        mma_bf16(I, a0h[mt], nh1a, nh1b);
                        mma_bf16(I, a0h[mt], nl1a, nl1b);
                        mma_bf16(I, a0l[mt], nh1a, nh1b);
                    }
        }

        // ---- magnitude gate -> P (split bf16 into smem), accumulate denom ----
#pragma unroll
        for (int mt = 0; mt < 2; mt++)
#pragma unroll
            for (int np = 0; np < 2; np++)
#pragma unroll
                for (int hf = 0; hf < 2; hf++) {
                    float* R = sr[mt][np * 2 + hf];
                    float* I = si_[mt][np * 2 + hf];
                    const int ycol = wn + np * 16 + hf * 8 + (lane & 3) * 2;
#pragma unroll
                    for (int jh = 0; jh < 2; jh++) {
                        const int row = wm + mt * 16 + (lane >> 2) + jh * 8;
                        const float re0 = R[jh * 2] * 0.125f, im0 = I[jh * 2] * 0.125f;
                        const float re1 = R[jh * 2 + 1] * 0.125f, im1 = I[jh * 2 + 1] * 0.125f;
                        const float m0 = __fsqrt_rn(re0 * re0 + im0 * im0);
                        const float m1 = __fsqrt_rn(re1 * re1 + im1 * im1);
                        const float w0 = 1.0f + 1.0f / (1.0f + __expf(-m0));
                        const float w1 = 1.0f + 1.0f / (1.0f + __expf(-m1));
                        dloc[mt][jh] += m0 * w0 + m1 * w1;
                        const float pr0 = re0 * w0, pr1 = re1 * w1;
                        const float pi0 = im0 * w0, pi1 = im1 * w1;
                        __nv_bfloat16 h0, l0, h1, l1;
                        split1(pr0, h0, l0); split1(pr1, h1, l1);
                        __nv_bfloat162 hp = {h0, h1}, lp = {l0, l1};
                        *(uint32_t*)(smc + APH + row * 272 + ycol * 2) = *(uint32_t*)&hp;
                        *(uint32_t*)(smc + APL + row * 272 + ycol * 2) = *(uint32_t*)&lp;
                        split1(pi0, h0, l0); split1(pi1, h1, l1);
                        __nv_bfloat162 hp2 = {h0, h1}, lp2 = {l0, l1};
                        *(uint32_t*)(smc + APH + row * 272 + 128 + ycol * 2) = *(uint32_t*)&hp2;
                        *(uint32_t*)(smc + APL + row * 272 + 128 + ycol * 2) = *(uint32_t*)&lp2;
                    }
                }
        __syncthreads();

        // ---- O += P @ Vf : A = P [x][Pr|Pi], B = V [e][Vr|Vi] ----
        for (int p = 0; p < 4; p++) {
            const int c0 = p * 16, c1 = c0 + 64;
            uint32_t a0h[2][4], a0l[2][4], a1h[2][4], a1l[2][4];
#pragma unroll
            for (int mt = 0; mt < 2; mt++) {
                const uint32_t rowb = sb + APH + (wm + mt * 16 + rA) * 272;
                uint32_t ad = rowb + (c0 + kA) * 2;
                ldsm4(a0h[mt], ad); ldsm4(a0l[mt], ad + (APL - APH));
                ad = rowb + (c1 + kA) * 2;
                ldsm4(a1h[mt], ad); ldsm4(a1l[mt], ad + (APL - APH));
            }
            uint32_t b0h[2][4], b0l[2][4], b1h[2][4], b1l[2][4];
#pragma unroll
            for (int np = 0; np < 2; np++) {
                const uint32_t rowb = sb + AVH + (wn + np * 16 + nB) * 272;
                uint32_t ad = rowb + (c0 + kB) * 2;
                ldsm4(b0h[np], ad); ldsm4(b0l[np], ad + (AVL - AVH));
                ad = rowb + (c1 + kB) * 2;
                ldsm4(b1h[np], ad); ldsm4(b1l[np], ad + (AVL - AVH));
            }
#pragma unroll
            for (int mt = 0; mt < 2; mt++)
#pragma unroll
                for (int np = 0; np < 2; np++)
#pragma unroll
                    for (int hf = 0; hf < 2; hf++) {
                        float* Or = orr[mt][np * 2 + hf];
                        float* Oi = oii[mt][np * 2 + hf];
                        const uint32_t h0a = b0h[np][hf * 2], h0b = b0h[np][hf * 2 + 1];
                        const uint32_t l0a = b0l[np][hf * 2], l0b = b0l[np][hf * 2 + 1];
                        const uint32_t h1a = b1h[np][hf * 2], h1b = b1h[np][hf * 2 + 1];
                        const uint32_t l1a = b1l[np][hf * 2], l1b = b1l[np][hf * 2 + 1];
                        const uint32_t nh1a = h1a ^ SGN2, nh1b = h1b ^ SGN2;
                        const uint32_t nl1a = l1a ^ SGN2, nl1b = l1b ^ SGN2;
                        // or = Pr*Vr - Pi*Vi
                        mma_bf16(Or, a0h[mt], h0a, h0b);
                        mma_bf16(Or, a0h[mt], l0a, l0b);
                        mma_bf16(Or, a0l[mt], h0a, h0b);
                        mma_bf16(Or, a1h[mt], nh1a, nh1b);
                        mma_bf16(Or, a1h[mt], nl1a, nl1b);
                        mma_bf16(Or, a1l[mt], nh1a, nh1b);
                        // oi = Pr*Vi + Pi*Vr
                        mma_bf16(Oi, a0h[mt], h1a, h1b);
                        mma_bf16(Oi, a0h[mt], l1a, l1b);
                        mma_bf16(Oi, a0l[mt], h1a, h1b);
                        mma_bf16(Oi, a1h[mt], h0a, h0b);
                        mma_bf16(Oi, a1h[mt], l0a, l0b);
                        mma_bf16(Oi, a1l[mt], h0a, h0b);
                    }
        }
        __syncthreads();
    }

    // ---- denominator reduce (deterministic slots) ----
    float* dp = (float*)(smc + ADP);
#pragma unroll
    for (int mt = 0; mt < 2; mt++)
#pragma unroll
        for (int jh = 0; jh < 2; jh++) {
            const int row = wm + mt * 16 + (lane >> 2) + jh * 8;
            dp[row * 8 + nwidx * 4 + (lane & 3)] = dloc[mt][jh];
        }
    __syncthreads();

#pragma unroll
    for (int mt = 0; mt < 2; mt++)
#pragma unroll
        for (int jh = 0; jh < 2; jh++) {
            const int row = wm + mt * 16 + (lane >> 2) + jh * 8;
            const int x = x0 + row;
            if (x >= LF) continue;
            float dn = 0.f;
#pragma unroll
            for (int t = 0; t < 8; t++) dn += dp[row * 8 + t];
            const float inv = 1.0f / fmaxf(dn, 1e-12f);
#pragma unroll
            for (int np = 0; np < 2; np++)
#pragma unroll
                for (int hf = 0; hf < 2; hf++) {
                    const int e0 = wn + np * 16 + hf * 8 + (lane & 3) * 2;
                    const float* Or = orr[mt][np * 2 + hf];
                    const float* Oi = oii[mt][np * 2 + hf];
                    const int j0 = jh * 2, j1 = jh * 2 + 1;
                    float4 v = make_float4(Or[j0] * inv, Oi[j0] * inv,
                                           Or[j1] * inv, Oi[j1] * inv);
                    *(float4*)(g_of + ((size_t)(bh * LF + x)) * 64 + e0) = v;
                }
        }
}

// =============== inverse: Hermitian extension + iFFT (ortho) ===============
__global__ __launch_bounds__(256) void k_fft_inv(float* __restrict__ out) {
    __shared__ float2 s0[1056];
    __shared__ float2 s1[1056];
    const int seq = blockIdx.x;             // bh*64 + e
    const int bh = seq >> 6, e = seq & 63;
    const float2* ip = g_of + (size_t)bh * LF * 64 + e;
    const int tid = threadIdx.x;
    for (int xx = tid; xx < 1024; xx += 256) {
        float2 v;
        if (xx <= 512) {
            v = ip[(size_t)xx * 64];
        } else {
            const float2 t = ip[(size_t)(1024 - xx) * 64];
            v = make_float2(t.x, -t.y);
        }
        s0[SKW(xx)] = v;
    }
    __syncthreads();
    fft1024_r4(s0, s1, tid, +1.0f);          // result in s1
    const int b = bh >> 3, h = bh & 7;
    float* op = out + (size_t)b * 1024 * 512 + h * 64 + e;
    const float sc = 1.0f / 32.0f;
    for (int l = tid; l < 1024; l += 256) op[(size_t)l * 512] = s1[SKW(l)].x * sc;
}

// ============================ launch ============================
extern "C" void kernel_launch(void* const* d_in, const int* in_sizes, int n_in,
                              void* d_out, int out_size) {
    const float* q    = (const float*)d_in[0];
    const float* k    = (const float*)d_in[1];
    const float* v    = (const float*)d_in[2];
    const float* W    = (const float*)d_in[3];
    const float* bias = (const float*)d_in[4];
    float* out = (float*)d_out;

    cudaFuncSetAttribute(k_conv_mma, cudaFuncAttributeMaxDynamicSharedMemorySize,
                         (int)CONV_SMEM);
    cudaFuncSetAttribute(k_attn_mma, cudaFuncAttributeMaxDynamicSharedMemorySize,
                         (int)ATTN_SMEM2);

    k_transpose_w<<<(1024 * 512 * 3 + 255) / 256, 256>>>(W);
    k_conv_mma<<<dim3(8, 128), 256, CONV_SMEM>>>(q, bias);
    k_fft_fwd<<<8192, 256>>>(nullptr, 0);   // q2 (GLU of conv output)
    k_fft_fwd<<<8192, 256>>>(k, 1);
    k_fft_fwd<<<8192, 256>>>(v, 2);
    k_attn_mma<<<dim3(128, 5), 256, ATTN_SMEM2>>>();
    k_fft_inv<<<8192, 256>>>(out);
}

// round 15
// speedup vs baseline: 2.3569x; 1.0407x over previous
#include <cuda_runtime.h>
#include <cuda_bf16.h>
#include <math.h>
#include <stdint.h>

// Problem constants: B=16, L=S=1024, H=8, E=64, d=512
#define LSEQ 1024
#define LF   513
#define NBH  128            // B*H

// -------- scratch (device globals; no allocation allowed) --------
__device__ __align__(256) float  g_y  [16777216];     // conv output [B*L][1024]
__device__ __align__(256) float2 g_of[(size_t)NBH * LF * 64];
// bf16 split planes of conv inputs
__device__ __align__(256) __nv_bfloat16 g_xh[(size_t)16 * 1024 * 512];
__device__ __align__(256) __nv_bfloat16 g_xl[(size_t)16 * 1024 * 512];
__device__ __align__(256) __nv_bfloat16 g_wh[(size_t)1024 * 1536];
__device__ __align__(256) __nv_bfloat16 g_wl[(size_t)1024 * 1536];
// bf16 split planes for attention (MMA-native layouts, zero-padded)
__device__ __align__(256) __nv_bfloat16 g_qsp_h[(size_t)NBH * 128 * 640];
__device__ __align__(256) __nv_bfloat16 g_qsp_l[(size_t)NBH * 128 * 640];
__device__ __align__(256) __nv_bfloat16 g_ksp_h[(size_t)NBH * 128 * 576];
__device__ __align__(256) __nv_bfloat16 g_ksp_l[(size_t)NBH * 128 * 576];
__device__ __align__(256) __nv_bfloat16 g_vsp_h[(size_t)NBH * 64 * 1152];
__device__ __align__(256) __nv_bfloat16 g_vsp_l[(size_t)NBH * 64 * 1152];

// ==================== helpers (base-target PTX only) ====================
__device__ __forceinline__ uint32_t smem_u32(const void* p) {
    uint32_t a;
    asm("{ .reg .u64 t; cvta.to.shared.u64 t, %1; cvt.u32.u64 %0, t; }" : "=r"(a) : "l"(p));
    return a;
}
__device__ __forceinline__ void ldsm4(uint32_t* r, uint32_t addr) {
    asm volatile("ldmatrix.sync.aligned.m8n8.x4.shared.b16 {%0,%1,%2,%3}, [%4];"
                 : "=r"(r[0]), "=r"(r[1]), "=r"(r[2]), "=r"(r[3]) : "r"(addr));
}
__device__ __forceinline__ void ldsm4t(uint32_t* r, uint32_t addr) {
    asm volatile("ldmatrix.sync.aligned.m8n8.x4.trans.shared.b16 {%0,%1,%2,%3}, [%4];"
                 : "=r"(r[0]), "=r"(r[1]), "=r"(r[2]), "=r"(r[3]) : "r"(addr));
}
__device__ __forceinline__ void mma_bf16(float* c, const uint32_t* a, uint32_t b0, uint32_t b1) {
    asm volatile("mma.sync.aligned.m16n8k16.row.col.f32.bf16.bf16.f32 "
                 "{%0,%1,%2,%3}, {%4,%5,%6,%7}, {%8,%9}, {%0,%1,%2,%3};"
                 : "+f"(c[0]), "+f"(c[1]), "+f"(c[2]), "+f"(c[3])
                 : "r"(a[0]), "r"(a[1]), "r"(a[2]), "r"(a[3]), "r"(b0), "r"(b1));
}
#define CP16(dst, src)      asm volatile("cp.async.cg.shared.global [%0], [%1], 16;" :: "r"(dst), "l"(src))
#define CP16Z(dst, src, sz) asm volatile("cp.async.cg.shared.global [%0], [%1], 16, %2;" :: "r"(dst), "l"(src), "r"(sz))
#define CP_COMMIT()    asm volatile("cp.async.commit_group;" ::: "memory")
#define CP_WAIT0()     asm volatile("cp.async.wait_group 0;" ::: "memory")
#define CP_WAIT1()     asm volatile("cp.async.wait_group 1;" ::: "memory")
#define SGN2 0x80008000u

__device__ __forceinline__ void split1(float v, __nv_bfloat16& h, __nv_bfloat16& l) {
    h = __float2bfloat16_rn(v);
    l = __float2bfloat16_rn(v - __bfloat162float(h));
}

// =============== prep: split x into bf16 hi/lo planes ===============
__global__ void k_split_x(const float* __restrict__ x) {
    const size_t i = ((size_t)blockIdx.x * 256 + threadIdx.x) * 2;
    const float2 v = *(const float2*)(x + i);
    __nv_bfloat16 h0, l0, h1, l1;
    split1(v.x, h0, l0);
    split1(v.y, h1, l1);
    __nv_bfloat162 hh = {h0, h1}, ll = {l0, l1};
    *(__nv_bfloat162*)(g_xh + i) = hh;
    *(__nv_bfloat162*)(g_xl + i) = ll;
}

// =============== W permute+split: W[o][i][t] -> g_wh/g_wl [o][t*512+i] ===============
__global__ void k_transpose_w(const float* __restrict__ W) {
    int idx = blockIdx.x * blockDim.x + threadIdx.x;
    if (idx >= 1024 * 512 * 3) return;
    int o = idx / 1536;
    int r = idx - o * 1536;
    int i = r / 3;
    int t = r - i * 3;
    __nv_bfloat16 h, l;
    split1(W[idx], h, l);
    g_wh[(size_t)o * 1536 + t * 512 + i] = h;
    g_wl[(size_t)o * 1536 + t * 512 + i] = l;
}

// =============== Conv1d im2col GEMM via mma.sync bf16 (split hi/lo) ===============
// 3-stage cp.async pipeline; smem stage (40960 B): Ah@0, Al@10240, Wh@20480, Wl@30720,
// 80 B row stride (64 B payload).
#define CONV_SMEM (3 * 40960)

__global__ void __launch_bounds__(256, 1)
k_conv_mma(const float* __restrict__ x, const float* __restrict__ bias) {
    extern __shared__ char smem[];
    const uint32_t sb = smem_u32(smem);
    const int tid = threadIdx.x, lane = tid & 31, wid = tid >> 5;
    const int m0 = blockIdx.y * 128, n0 = blockIdx.x * 128;
    const int warp_m = (wid & 3) * 32, warp_n = (wid >> 2) * 64;

    const int rA = (lane & 7) + (lane & 8);
    const int kA = ((lane >> 4) & 1) * 8;
    const int nB = (lane & 7) + ((lane >> 4) & 1) * 8;
    const int kB = ((lane >> 3) & 1) * 8;

    float c[2][8][4];
#pragma unroll
    for (int mt = 0; mt < 2; mt++)
#pragma unroll
        for (int nt = 0; nt < 8; nt++)
#pragma unroll
            for (int r = 0; r < 4; r++) c[mt][nt][r] = 0.f;

    // cp.async tile loader: A (im2col, halo zero-fill) + W, bf16 planes
    auto load_tile = [&](int kt) {
        const int tap = kt >> 4;                // (kt*32)/512
        const int kbase = (kt * 32) & 511;
        const uint32_t dbase = sb + (kt % 3) * 40960;
#pragma unroll
        for (int i = 0; i < 2; i++) {
            const int slot = tid + i * 256;     // 0..511
            const int row = slot >> 2, ch8 = (slot & 3) * 8;
            const uint32_t d = dbase + row * 80 + (slot & 3) * 16;
            // A
            const int m = m0 + row, bb = m >> 10, l = m & 1023;
            const int lp = l + tap - 1;
            const uint32_t ok = (lp >= 0 && lp < 1024) ? 16u : 0u;
            const int lpc = lp < 0 ? 0 : (lp > 1023 ? 1023 : lp);
            const size_t aoff = ((size_t)bb * 1024 + lpc) * 512 + kbase + ch8;
            CP16Z(d,         (const char*)(g_xh + aoff), ok);
            CP16Z(d + 10240, (const char*)(g_xl + aoff), ok);
            // W
            const size_t woff = (size_t)(n0 + row) * 1536 + kt * 32 + ch8;
            CP16(d + 20480, (const char*)(g_wh + woff));
            CP16(d + 30720, (const char*)(g_wl + woff));
        }
    };

    load_tile(0); CP_COMMIT();
    load_tile(1); CP_COMMIT();

    for (int kt = 0; kt < 48; kt++) {
        CP_WAIT1();
        __syncthreads();

        const uint32_t sbase = sb + (kt % 3) * 40960;
#pragma unroll
        for (int ks = 0; ks < 2; ks++) {
            uint32_t ah[2][4], al[2][4];
#pragma unroll
            for (int mt = 0; mt < 2; mt++) {
                const uint32_t aaddr = sbase + (warp_m + mt * 16 + rA) * 80 + (ks * 16 + kA) * 2;
                ldsm4(ah[mt], aaddr);
                ldsm4(al[mt], aaddr + 10240);
            }
            uint32_t bh[4][4], bl[4][4];
#pragma unroll
            for (int np = 0; np < 4; np++) {
                const uint32_t baddr = sbase + 20480 + (warp_n + np * 16 + nB) * 80 + (ks * 16 + kB) * 2;
                ldsm4(bh[np], baddr);
                ldsm4(bl[np], baddr + 10240);
            }
#pragma unroll
            for (int mt = 0; mt < 2; mt++)
#pragma unroll
                for (int np = 0; np < 4; np++)
#pragma unroll
                    for (int half = 0; half < 2; half++) {
                        float* cc = c[mt][np * 2 + half];
                        const uint32_t bh0 = bh[np][half * 2], bh1 = bh[np][half * 2 + 1];
                        const uint32_t bl0 = bl[np][half * 2], bl1 = bl[np][half * 2 + 1];
                        mma_bf16(cc, ah[mt], bh0, bh1);
                        mma_bf16(cc, ah[mt], bl0, bl1);
                        mma_bf16(cc, al[mt], bh0, bh1);
                    }
        }

        if (kt < 46) load_tile(kt + 2);
        CP_COMMIT();
    }

#pragma unroll
    for (int mt = 0; mt < 2; mt++) {
        const int row0 = m0 + warp_m + mt * 16 + (lane >> 2);
#pragma unroll
        for (int nt = 0; nt < 8; nt++) {
            const int col = n0 + warp_n + nt * 8 + (lane & 3) * 2;
            const float2 bv = *(const float2*)(bias + col);
            *(float2*)(g_y + (size_t)row0 * 1024 + col) =
                make_float2(c[mt][nt][0] + bv.x, c[mt][nt][1] + bv.y);
            *(float2*)(g_y + (size_t)(row0 + 8) * 1024 + col) =
                make_float2(c[mt][nt][2] + bv.x, c[mt][nt][3] + bv.y);
        }
    }
}

// =============== 1024-pt radix-4 Stockham FFT in shared memory ===============
#define SKW(i) ((i) + ((i) >> 5))

__device__ __forceinline__ float2 cmul(float2 a, float2 b) {
    return make_float2(a.x * b.x - a.y * b.y, a.x * b.y + a.y * b.x);
}

__device__ __forceinline__ void fft1024_r4(float2* s0, float2* s1, int tid, float sign) {
    float2* src = s0;
    float2* dst = s1;
    int n = 1024;
    int logstr = 0;
#pragma unroll
    for (int st = 0; st < 5; st++) {
        const int mq = n >> 2;
        const int str = 1 << logstr;
        const int p = tid >> logstr;
        const int q = tid & (str - 1);
        const int base = q + str * p;
        const int offc = str * mq;
        const float2 x0 = src[SKW(base)];
        const float2 x1 = src[SKW(base + offc)];
        const float2 x2 = src[SKW(base + 2 * offc)];
        const float2 x3 = src[SKW(base + 3 * offc)];
        const float2 a  = make_float2(x0.x + x2.x, x0.y + x2.y);
        const float2 b  = make_float2(x0.x - x2.x, x0.y - x2.y);
        const float2 cc = make_float2(x1.x + x3.x, x1.y + x3.y);
        const float2 dd = make_float2(x1.x - x3.x, x1.y - x3.y);
        const float2 idd = make_float2(-sign * dd.y, sign * dd.x);
        float sw, cw;
        sincospif(sign * 2.0f * (float)p / (float)n, &sw, &cw);
        const float2 w1 = make_float2(cw, sw);
        const float2 w2 = cmul(w1, w1);
        const float2 w3 = cmul(w1, w2);
        const int ob = q + str * 4 * p;
        dst[SKW(ob)]           = make_float2(a.x + cc.x, a.y + cc.y);
        dst[SKW(ob + str)]     = cmul(w1, make_float2(b.x + idd.x, b.y + idd.y));
        dst[SKW(ob + str * 2)] = cmul(w2, make_float2(a.x - cc.x, a.y - cc.y));
        dst[SKW(ob + str * 3)] = cmul(w3, make_float2(b.x - idd.x, b.y - idd.y));
        __syncthreads();
        float2* tp = src; src = dst; dst = tp;
        n >>= 2;
        logstr += 2;
    }
}

// =============== forward rFFT (ortho) -> bf16 split planes ===============
__global__ __launch_bounds__(256) void k_fft_fwd(const float* __restrict__ in, int mode) {
    __shared__ float2 s0[1056];
    __shared__ float2 s1[1056];
    const int seq = blockIdx.x;              // b*512 + c,  c = h*64+e
    const int b = seq >> 9, c = seq & 511;
    const int tid = threadIdx.x;
    for (int l = tid; l < 1024; l += 256) {
        float v;
        if (mode == 0) {
            const float* yr = g_y + ((size_t)(b * 1024 + l)) * 1024;
            const float a = yr[c];
            const float g = yr[c + 512];
            v = a * (1.0f / (1.0f + __expf(-g)));
        } else {
            v = in[((size_t)(b * 1024 + l)) * 512 + c];
        }
        s0[SKW(l)] = make_float2(v, 0.f);
    }
    __syncthreads();
    fft1024_r4(s0, s1, tid, -1.0f);          // result in s1
    const int bh = b * 8 + (c >> 6), e = c & 63;
    const float sc = 1.0f / 32.0f;
    if (mode == 2) {
        __nv_bfloat16* vh = g_vsp_h + ((size_t)(bh * 64 + e)) * 1152;
        __nv_bfloat16* vl = g_vsp_l + ((size_t)(bh * 64 + e)) * 1152;
        for (int xx = tid; xx < 576; xx += 256) {
            float re = 0.f, im = 0.f;
            if (xx < LF) { re = s1[SKW(xx)].x * sc; im = s1[SKW(xx)].y * sc; }
            __nv_bfloat16 h, l;
            split1(re, h, l); vh[xx] = h; vl[xx] = l;
            split1(im, h, l); vh[576 + xx] = h; vl[576 + xx] = l;
        }
    } else {
        const int width = (mode == 0) ? 640 : 576;
        __nv_bfloat16* base_h = (mode == 0) ? g_qsp_h : g_ksp_h;
        __nv_bfloat16* base_l = (mode == 0) ? g_qsp_l : g_ksp_l;
        __nv_bfloat16* rh = base_h + ((size_t)(bh * 128 + e)) * width;
        __nv_bfloat16* rl = base_l + ((size_t)(bh * 128 + e)) * width;
        __nv_bfloat16* ih = base_h + ((size_t)(bh * 128 + 64 + e)) * width;
        __nv_bfloat16* il = base_l + ((size_t)(bh * 128 + 64 + e)) * width;
        for (int xx = tid; xx < width; xx += 256) {
            float re = 0.f, im = 0.f;
            if (xx < LF) { re = s1[SKW(xx)].x * sc; im = s1[SKW(xx)].y * sc; }
            __nv_bfloat16 h, l;
            split1(re, h, l); rh[xx] = h; rl[xx] = l;
            split1(im, h, l); ih[xx] = h; il[xx] = l;
        }
    }
}

// =============== frequency-domain attention on mma.sync (split bf16) ===============
#define AQH 0
#define AQL 34816
#define AKH 69632
#define AKL 88064
#define AVH 106496
#define AVL 123904
#define APH 141312
#define APL 176128
#define ADP 210944
#define ATTN_SMEM2 215040

__global__ void __launch_bounds__(256, 1) k_attn_mma() {
    extern __shared__ char smc[];
    const uint32_t sb = smem_u32(smc);
    const int tid = threadIdx.x, lane = tid & 31, wid = tid >> 5;
    const int bh = blockIdx.x, x0 = blockIdx.y * 128;
    const int wm = (wid & 3) * 32, wn = (wid >> 2) * 32, nwidx = wid >> 2;

    const int kTa = (lane & 7) + ((lane >> 4) & 1) * 8;
    const int mTa = ((lane >> 3) & 1) * 8;
    const int kTb = (lane & 7) + ((lane >> 3) & 1) * 8;
    const int nTb = ((lane >> 4) & 1) * 8;
    const int rA = (lane & 7) + (lane & 8);
    const int kA = ((lane >> 4) & 1) * 8;
    const int nB = (lane & 7) + ((lane >> 4) & 1) * 8;
    const int kB = ((lane >> 3) & 1) * 8;

    float sr[2][4][4], si_[2][4][4], orr[2][4][4], oii[2][4][4];
#pragma unroll
    for (int mt = 0; mt < 2; mt++)
#pragma unroll
        for (int t = 0; t < 4; t++)
#pragma unroll
            for (int r = 0; r < 4; r++) { orr[mt][t][r] = 0.f; oii[mt][t][r] = 0.f; }
    float dloc[2][2] = {{0.f, 0.f}, {0.f, 0.f}};

#pragma unroll
    for (int i = 0; i < 8; i++) {
        const int cc = tid + i * 256;
        const int row = cc >> 4, off = (cc & 15) * 16;
        const char* sh = (const char*)(g_qsp_h + ((size_t)(bh * 128 + row)) * 640 + x0) + off;
        const char* sl = (const char*)(g_qsp_l + ((size_t)(bh * 128 + row)) * 640 + x0) + off;
        CP16(sb + AQH + row * 272 + off, sh);
        CP16(sb + AQL + row * 272 + off, sl);
    }
    CP_COMMIT();

    for (int yt = 0; yt < 9; yt++) {
#pragma unroll
        for (int i = 0; i < 4; i++) {
            const int cc = tid + i * 256;
            const int row = cc >> 3, off = (cc & 7) * 16;
            const char* sh = (const char*)(g_ksp_h + ((size_t)(bh * 128 + row)) * 576 + yt * 64) + off;
            const char* sl = (const char*)(g_ksp_l + ((size_t)(bh * 128 + row)) * 576 + yt * 64) + off;
            CP16(sb + AKH + row * 144 + off, sh);
            CP16(sb + AKL + row * 144 + off, sl);
        }
#pragma unroll
        for (int i = 0; i < 4; i++) {
            const int cc = tid + i * 256;
            const int row = cc >> 4, seg = (cc >> 3) & 1, off = (cc & 7) * 16;
            const char* sh = (const char*)(g_vsp_h + ((size_t)(bh * 64 + row)) * 1152 + seg * 576 + yt * 64) + off;
            const char* sl = (const char*)(g_vsp_l + ((size_t)(bh * 64 + row)) * 1152 + seg * 576 + yt * 64) + off;
            CP16(sb + AVH + row * 272 + seg * 128 + off, sh);
            CP16(sb + AVL + row * 272 + seg * 128 + off, sl);
        }
        CP_COMMIT();
        CP_WAIT0();
        __syncthreads();

#pragma unroll
        for (int mt = 0; mt < 2; mt++)
#pragma unroll
            for (int t = 0; t < 4; t++)
#pragma unroll
                for (int r = 0; r < 4; r++) { sr[mt][t][r] = 0.f; si_[mt][t][r] = 0.f; }

        for (int p = 0; p < 4; p++) {
            const int c0 = p * 16, c1 = c0 + 64;
            uint32_t a0h[2][4], a0l[2][4], a1h[2][4], a1l[2][4];
#pragma unroll
            for (int mt = 0; mt < 2; mt++) {
                const uint32_t col = (wm + mt * 16 + mTa) * 2;
                uint32_t ad = sb + AQH + (c0 + kTa) * 272 + col;
                ldsm4t(a0h[mt], ad); ldsm4t(a0l[mt], ad + (AQL - AQH));
                ad = sb + AQH + (c1 + kTa) * 272 + col;
                ldsm4t(a1h[mt], ad); ldsm4t(a1l[mt], ad + (AQL - AQH));
            }
            uint32_t b0h[2][4], b0l[2][4], b1h[2][4], b1l[2][4];
#pragma unroll
            for (int np = 0; np < 2; np++) {
                const uint32_t col = (wn + np * 16 + nTb) * 2;
                uint32_t ad = sb + AKH + (c0 + kTb) * 144 + col;
                ldsm4t(b0h[np], ad); ldsm4t(b0l[np], ad + (AKL - AKH));
                ad = sb + AKH + (c1 + kTb) * 144 + col;
                ldsm4t(b1h[np], ad); ldsm4t(b1l[np], ad + (AKL - AKH));
            }
#pragma unroll
            for (int mt = 0; mt < 2; mt++)
#pragma unroll
                for (int np = 0; np < 2; np++)
#pragma unroll
                    for (int hf = 0; hf < 2; hf++) {
                        float* R = sr[mt][np * 2 + hf];
                        float* I = si_[mt][np * 2 + hf];
                        const uint32_t h0a = b0h[np][hf * 2], h0b = b0h[np][hf * 2 + 1];
                        const uint32_t l0a = b0l[np][hf * 2], l0b = b0l[np][hf * 2 + 1];
                        const uint32_t h1a = b1h[np][hf * 2], h1b = b1h[np][hf * 2 + 1];
                        const uint32_t l1a = b1l[np][hf * 2], l1b = b1l[np][hf * 2 + 1];
                        const uint32_t nh1a = h1a ^ SGN2, nh1b = h1b ^ SGN2;
                        const uint32_t nl1a = l1a ^ SGN2, nl1b = l1b ^ SGN2;
                        mma_bf16(R, a0h[mt], h0a, h0b);
                        mma_bf16(R, a0h[mt], l0a, l0b);
                        mma_bf16(R, a0l[mt], h0a, h0b);
                        mma_bf16(R, a1h[mt], h1a, h1b);
                        mma_bf16(R, a1h[mt], l1a, l1b);
                        mma_bf16(R, a1l[mt], h1a, h1b);
                        mma_bf16(I, a1h[mt], h0a, h0b);
                        mma_bf16(I, a1h[mt], l0a, l0b);
                        mma_bf16(I, a1l[mt], h0a, h0b);
                        mma_bf16(I, a0h[mt], nh1a, nh1b);
                        mma_bf16(I, a0h[mt], nl1a, nl1b);
                        mma_bf16(I, a0l[mt], nh1a, nh1b);
                    }
        }

#pragma unroll
        for (int mt = 0; mt < 2; mt++)
#pragma unroll
            for (int np = 0; np < 2; np++)
#pragma unroll
                for (int hf = 0; hf < 2; hf++) {
                    float* R = sr[mt][np * 2 + hf];
                    float* I = si_[mt][np * 2 + hf];
                    const int ycol = wn + np * 16 + hf * 8 + (lane & 3) * 2;
#pragma unroll
                    for (int jh = 0; jh < 2; jh++) {
                        const int row = wm + mt * 16 + (lane >> 2) + jh * 8;
                        const float re0 = R[jh * 2] * 0.125f, im0 = I[jh * 2] * 0.125f;
                        const float re1 = R[jh * 2 + 1] * 0.125f, im1 = I[jh * 2 + 1] * 0.125f;
                        const float m0 = __fsqrt_rn(re0 * re0 + im0 * im0);
                        const float m1 = __fsqrt_rn(re1 * re1 + im1 * im1);
                        const float w0 = 1.0f + 1.0f / (1.0f + __expf(-m0));
                        const float w1 = 1.0f + 1.0f / (1.0f + __expf(-m1));
                        dloc[mt][jh] += m0 * w0 + m1 * w1;
                        const float pr0 = re0 * w0, pr1 = re1 * w1;
                        const float pi0 = im0 * w0, pi1 = im1 * w1;
                        __nv_bfloat16 h0, l0, h1, l1;
                        split1(pr0, h0, l0); split1(pr1, h1, l1);
                        __nv_bfloat162 hp = {h0, h1}, lp = {l0, l1};
                        *(uint32_t*)(smc + APH + row * 272 + ycol * 2) = *(uint32_t*)&hp;
                        *(uint32_t*)(smc + APL + row * 272 + ycol * 2) = *(uint32_t*)&lp;
                        split1(pi0, h0, l0); split1(pi1, h1, l1);
                        __nv_bfloat162 hp2 = {h0, h1}, lp2 = {l0, l1};
                        *(uint32_t*)(smc + APH + row * 272 + 128 + ycol * 2) = *(uint32_t*)&hp2;
                        *(uint32_t*)(smc + APL + row * 272 + 128 + ycol * 2) = *(uint32_t*)&lp2;
                    }
                }
        __syncthreads();

        for (int p = 0; p < 4; p++) {
            const int c0 = p * 16, c1 = c0 + 64;
            uint32_t a0h[2][4], a0l[2][4], a1h[2][4], a1l[2][4];
#pragma unroll
            for (int mt = 0; mt < 2; mt++) {
                const uint32_t rowb = sb + APH + (wm + mt * 16 + rA) * 272;
                uint32_t ad = rowb + (c0 + kA) * 2;
                ldsm4(a0h[mt], ad); ldsm4(a0l[mt], ad + (APL - APH));
                ad = rowb + (c1 + kA) * 2;
                ldsm4(a1h[mt], ad); ldsm4(a1l[mt], ad + (APL - APH));
            }
            uint32_t b0h[2][4], b0l[2][4], b1h[2][4], b1l[2][4];
#pragma unroll
            for (int np = 0; np < 2; np++) {
                const uint32_t rowb = sb + AVH + (wn + np * 16 + nB) * 272;
                uint32_t ad = rowb + (c0 + kB) * 2;
                ldsm4(b0h[np], ad); ldsm4(b0l[np], ad + (AVL - AVH));
                ad = rowb + (c1 + kB) * 2;
                ldsm4(b1h[np], ad); ldsm4(b1l[np], ad + (AVL - AVH));
            }
#pragma unroll
            for (int mt = 0; mt < 2; mt++)
#pragma unroll
                for (int np = 0; np < 2; np++)
#pragma unroll
                    for (int hf = 0; hf < 2; hf++) {
                        float* Or = orr[mt][np * 2 + hf];
                        float* Oi = oii[mt][np * 2 + hf];
                        const uint32_t h0a = b0h[np][hf * 2], h0b = b0h[np][hf * 2 + 1];
                        const uint32_t l0a = b0l[np][hf * 2], l0b = b0l[np][hf * 2 + 1];
                        const uint32_t h1a = b1h[np][hf * 2], h1b = b1h[np][hf * 2 + 1];
                        const uint32_t l1a = b1l[np][hf * 2], l1b = b1l[np][hf * 2 + 1];
                        const uint32_t nh1a = h1a ^ SGN2, nh1b = h1b ^ SGN2;
                        const uint32_t nl1a = l1a ^ SGN2, nl1b = l1b ^ SGN2;
                        mma_bf16(Or, a0h[mt], h0a, h0b);
                        mma_bf16(Or, a0h[mt], l0a, l0b);
                        mma_bf16(Or, a0l[mt], h0a, h0b);
                        mma_bf16(Or, a1h[mt], nh1a, nh1b);
                        mma_bf16(Or, a1h[mt], nl1a, nl1b);
                        mma_bf16(Or, a1l[mt], nh1a, nh1b);
                        mma_bf16(Oi, a0h[mt], h1a, h1b);
                        mma_bf16(Oi, a0h[mt], l1a, l1b);
                        mma_bf16(Oi, a0l[mt], h1a, h1b);
                        mma_bf16(Oi, a1h[mt], h0a, h0b);
                        mma_bf16(Oi, a1h[mt], l0a, l0b);
                        mma_bf16(Oi, a1l[mt], h0a, h0b);
                    }
        }
        __syncthreads();
    }

    float* dp = (float*)(smc + ADP);
#pragma unroll
    for (int mt = 0; mt < 2; mt++)
#pragma unroll
        for (int jh = 0; jh < 2; jh++) {
            const int row = wm + mt * 16 + (lane >> 2) + jh * 8;
            dp[row * 8 + nwidx * 4 + (lane & 3)] = dloc[mt][jh];
        }
    __syncthreads();

#pragma unroll
    for (int mt = 0; mt < 2; mt++)
#pragma unroll
        for (int jh = 0; jh < 2; jh++) {
            const int row = wm + mt * 16 + (lane >> 2) + jh * 8;
            const int x = x0 + row;
            if (x >= LF) continue;
            float dn = 0.f;
#pragma unroll
            for (int t = 0; t < 8; t++) dn += dp[row * 8 + t];
            const float inv = 1.0f / fmaxf(dn, 1e-12f);
#pragma unroll
            for (int np = 0; np < 2; np++)
#pragma unroll
                for (int hf = 0; hf < 2; hf++) {
                    const int e0 = wn + np * 16 + hf * 8 + (lane & 3) * 2;
                    const float* Or = orr[mt][np * 2 + hf];
                    const float* Oi = oii[mt][np * 2 + hf];
                    const int j0 = jh * 2, j1 = jh * 2 + 1;
                    float4 v = make_float4(Or[j0] * inv, Oi[j0] * inv,
                                           Or[j1] * inv, Oi[j1] * inv);
                    *(float4*)(g_of + ((size_t)(bh * LF + x)) * 64 + e0) = v;
                }
        }
}

// =============== inverse: Hermitian extension + iFFT (ortho) ===============
__global__ __launch_bounds__(256) void k_fft_inv(float* __restrict__ out) {
    __shared__ float2 s0[1056];
    __shared__ float2 s1[1056];
    const int seq = blockIdx.x;             // bh*64 + e
    const int bh = seq >> 6, e = seq & 63;
    const float2* ip = g_of + (size_t)bh * LF * 64 + e;
    const int tid = threadIdx.x;
    for (int xx = tid; xx < 1024; xx += 256) {
        float2 v;
        if (xx <= 512) {
            v = ip[(size_t)xx * 64];
        } else {
            const float2 t = ip[(size_t)(1024 - xx) * 64];
            v = make_float2(t.x, -t.y);
        }
        s0[SKW(xx)] = v;
    }
    __syncthreads();
    fft1024_r4(s0, s1, tid, +1.0f);          // result in s1
    const int b = bh >> 3, h = bh & 7;
    float* op = out + (size_t)b * 1024 * 512 + h * 64 + e;
    const float sc = 1.0f / 32.0f;
    for (int l = tid; l < 1024; l += 256) op[(size_t)l * 512] = s1[SKW(l)].x * sc;
}

// ============================ launch ============================
extern "C" void kernel_launch(void* const* d_in, const int* in_sizes, int n_in,
                              void* d_out, int out_size) {
    const float* q    = (const float*)d_in[0];
    const float* k    = (const float*)d_in[1];
    const float* v    = (const float*)d_in[2];
    const float* W    = (const float*)d_in[3];
    const float* bias = (const float*)d_in[4];
    float* out = (float*)d_out;

    cudaFuncSetAttribute(k_conv_mma, cudaFuncAttributeMaxDynamicSharedMemorySize,
                         (int)CONV_SMEM);
    cudaFuncSetAttribute(k_attn_mma, cudaFuncAttributeMaxDynamicSharedMemorySize,
                         (int)ATTN_SMEM2);

    k_split_x<<<16384, 256>>>(q);
    k_transpose_w<<<(1024 * 512 * 3 + 255) / 256, 256>>>(W);
    k_conv_mma<<<dim3(8, 128), 256, CONV_SMEM>>>(q, bias);
    k_fft_fwd<<<8192, 256>>>(nullptr, 0);   // q2 (GLU of conv output)
    k_fft_fwd<<<8192, 256>>>(k, 1);
    k_fft_fwd<<<8192, 256>>>(v, 2);
    k_attn_mma<<<dim3(128, 5), 256, ATTN_SMEM2>>>();
    k_fft_inv<<<8192, 256>>>(out);
}

// round 16
// speedup vs baseline: 2.5082x; 1.0642x over previous
#include <cuda_runtime.h>
#include <cuda_bf16.h>
#include <math.h>
#include <stdint.h>

// Problem constants: B=16, L=S=1024, H=8, E=64, d=512
#define LSEQ 1024
#define LF   513
#define NBH  128            // B*H

// -------- scratch (device globals; no allocation allowed) --------
__device__ __align__(256) float  g_y  [16777216];     // conv output [B*L][1024]
__device__ __align__(256) float2 g_of[(size_t)NBH * LF * 64];
// bf16 split planes of conv inputs
__device__ __align__(256) __nv_bfloat16 g_xh[(size_t)16 * 1024 * 512];
__device__ __align__(256) __nv_bfloat16 g_xl[(size_t)16 * 1024 * 512];
__device__ __align__(256) __nv_bfloat16 g_wh[(size_t)1024 * 1536];
__device__ __align__(256) __nv_bfloat16 g_wl[(size_t)1024 * 1536];
// bf16 split planes for attention (MMA-native layouts, zero-padded)
__device__ __align__(256) __nv_bfloat16 g_qsp_h[(size_t)NBH * 128 * 640];
__device__ __align__(256) __nv_bfloat16 g_qsp_l[(size_t)NBH * 128 * 640];
__device__ __align__(256) __nv_bfloat16 g_ksp_h[(size_t)NBH * 128 * 576];
__device__ __align__(256) __nv_bfloat16 g_ksp_l[(size_t)NBH * 128 * 576];
__device__ __align__(256) __nv_bfloat16 g_vsp_h[(size_t)NBH * 64 * 1152];
__device__ __align__(256) __nv_bfloat16 g_vsp_l[(size_t)NBH * 64 * 1152];

// ==================== helpers (base-target PTX only) ====================
__device__ __forceinline__ uint32_t smem_u32(const void* p) {
    uint32_t a;
    asm("{ .reg .u64 t; cvta.to.shared.u64 t, %1; cvt.u32.u64 %0, t; }" : "=r"(a) : "l"(p));
    return a;
}
__device__ __forceinline__ void ldsm4(uint32_t* r, uint32_t addr) {
    asm volatile("ldmatrix.sync.aligned.m8n8.x4.shared.b16 {%0,%1,%2,%3}, [%4];"
                 : "=r"(r[0]), "=r"(r[1]), "=r"(r[2]), "=r"(r[3]) : "r"(addr));
}
__device__ __forceinline__ void ldsm4t(uint32_t* r, uint32_t addr) {
    asm volatile("ldmatrix.sync.aligned.m8n8.x4.trans.shared.b16 {%0,%1,%2,%3}, [%4];"
                 : "=r"(r[0]), "=r"(r[1]), "=r"(r[2]), "=r"(r[3]) : "r"(addr));
}
__device__ __forceinline__ void mma_bf16(float* c, const uint32_t* a, uint32_t b0, uint32_t b1) {
    asm volatile("mma.sync.aligned.m16n8k16.row.col.f32.bf16.bf16.f32 "
                 "{%0,%1,%2,%3}, {%4,%5,%6,%7}, {%8,%9}, {%0,%1,%2,%3};"
                 : "+f"(c[0]), "+f"(c[1]), "+f"(c[2]), "+f"(c[3])
                 : "r"(a[0]), "r"(a[1]), "r"(a[2]), "r"(a[3]), "r"(b0), "r"(b1));
}
#define CP16(dst, src)      asm volatile("cp.async.cg.shared.global [%0], [%1], 16;" :: "r"(dst), "l"(src))
#define CP16Z(dst, src, sz) asm volatile("cp.async.cg.shared.global [%0], [%1], 16, %2;" :: "r"(dst), "l"(src), "r"(sz))
#define CP_COMMIT()    asm volatile("cp.async.commit_group;" ::: "memory")
#define CP_WAIT0()     asm volatile("cp.async.wait_group 0;" ::: "memory")
#define CP_WAIT1()     asm volatile("cp.async.wait_group 1;" ::: "memory")
#define SGN2 0x80008000u

__device__ __forceinline__ void split1(float v, __nv_bfloat16& h, __nv_bfloat16& l) {
    h = __float2bfloat16_rn(v);
    l = __float2bfloat16_rn(v - __bfloat162float(h));
}

// =============== prep: split x into bf16 hi/lo planes ===============
__global__ void k_split_x(const float* __restrict__ x) {
    const size_t i = ((size_t)blockIdx.x * 256 + threadIdx.x) * 2;
    const float2 v = *(const float2*)(x + i);
    __nv_bfloat16 h0, l0, h1, l1;
    split1(v.x, h0, l0);
    split1(v.y, h1, l1);
    __nv_bfloat162 hh = {h0, h1}, ll = {l0, l1};
    *(__nv_bfloat162*)(g_xh + i) = hh;
    *(__nv_bfloat162*)(g_xl + i) = ll;
}

// =============== W permute+split: W[o][i][t] -> g_wh/g_wl [o][t*512+i] ===============
__global__ void k_transpose_w(const float* __restrict__ W) {
    int idx = blockIdx.x * blockDim.x + threadIdx.x;
    if (idx >= 1024 * 512 * 3) return;
    int o = idx / 1536;
    int r = idx - o * 1536;
    int i = r / 3;
    int t = r - i * 3;
    __nv_bfloat16 h, l;
    split1(W[idx], h, l);
    g_wh[(size_t)o * 1536 + t * 512 + i] = h;
    g_wl[(size_t)o * 1536 + t * 512 + i] = l;
}

// =============== Conv1d im2col GEMM via mma.sync bf16 (split hi/lo) ===============
#define CONV_SMEM (3 * 40960)

__global__ void __launch_bounds__(256, 1)
k_conv_mma(const float* __restrict__ x, const float* __restrict__ bias) {
    extern __shared__ char smem[];
    const uint32_t sb = smem_u32(smem);
    const int tid = threadIdx.x, lane = tid & 31, wid = tid >> 5;
    const int m0 = blockIdx.y * 128, n0 = blockIdx.x * 128;
    const int warp_m = (wid & 3) * 32, warp_n = (wid >> 2) * 64;

    const int rA = (lane & 7) + (lane & 8);
    const int kA = ((lane >> 4) & 1) * 8;
    const int nB = (lane & 7) + ((lane >> 4) & 1) * 8;
    const int kB = ((lane >> 3) & 1) * 8;

    float c[2][8][4];
#pragma unroll
    for (int mt = 0; mt < 2; mt++)
#pragma unroll
        for (int nt = 0; nt < 8; nt++)
#pragma unroll
            for (int r = 0; r < 4; r++) c[mt][nt][r] = 0.f;

    auto load_tile = [&](int kt) {
        const int tap = kt >> 4;
        const int kbase = (kt * 32) & 511;
        const uint32_t dbase = sb + (kt % 3) * 40960;
#pragma unroll
        for (int i = 0; i < 2; i++) {
            const int slot = tid + i * 256;
            const int row = slot >> 2, ch8 = (slot & 3) * 8;
            const uint32_t d = dbase + row * 80 + (slot & 3) * 16;
            const int m = m0 + row, bb = m >> 10, l = m & 1023;
            const int lp = l + tap - 1;
            const uint32_t ok = (lp >= 0 && lp < 1024) ? 16u : 0u;
            const int lpc = lp < 0 ? 0 : (lp > 1023 ? 1023 : lp);
            const size_t aoff = ((size_t)bb * 1024 + lpc) * 512 + kbase + ch8;
            CP16Z(d,         (const char*)(g_xh + aoff), ok);
            CP16Z(d + 10240, (const char*)(g_xl + aoff), ok);
            const size_t woff = (size_t)(n0 + row) * 1536 + kt * 32 + ch8;
            CP16(d + 20480, (const char*)(g_wh + woff));
            CP16(d + 30720, (const char*)(g_wl + woff));
        }
    };

    load_tile(0); CP_COMMIT();
    load_tile(1); CP_COMMIT();

    for (int kt = 0; kt < 48; kt++) {
        CP_WAIT1();
        __syncthreads();

        const uint32_t sbase = sb + (kt % 3) * 40960;
#pragma unroll
        for (int ks = 0; ks < 2; ks++) {
            uint32_t ah[2][4], al[2][4];
#pragma unroll
            for (int mt = 0; mt < 2; mt++) {
                const uint32_t aaddr = sbase + (warp_m + mt * 16 + rA) * 80 + (ks * 16 + kA) * 2;
                ldsm4(ah[mt], aaddr);
                ldsm4(al[mt], aaddr + 10240);
            }
            uint32_t bh[4][4], bl[4][4];
#pragma unroll
            for (int np = 0; np < 4; np++) {
                const uint32_t baddr = sbase + 20480 + (warp_n + np * 16 + nB) * 80 + (ks * 16 + kB) * 2;
                ldsm4(bh[np], baddr);
                ldsm4(bl[np], baddr + 10240);
            }
#pragma unroll
            for (int mt = 0; mt < 2; mt++)
#pragma unroll
                for (int np = 0; np < 4; np++)
#pragma unroll
                    for (int half = 0; half < 2; half++) {
                        float* cc = c[mt][np * 2 + half];
                        const uint32_t bh0 = bh[np][half * 2], bh1 = bh[np][half * 2 + 1];
                        const uint32_t bl0 = bl[np][half * 2], bl1 = bl[np][half * 2 + 1];
                        mma_bf16(cc, ah[mt], bh0, bh1);
                        mma_bf16(cc, ah[mt], bl0, bl1);
                        mma_bf16(cc, al[mt], bh0, bh1);
                    }
        }

        if (kt < 46) load_tile(kt + 2);
        CP_COMMIT();
    }

#pragma unroll
    for (int mt = 0; mt < 2; mt++) {
        const int row0 = m0 + warp_m + mt * 16 + (lane >> 2);
#pragma unroll
        for (int nt = 0; nt < 8; nt++) {
            const int col = n0 + warp_n + nt * 8 + (lane & 3) * 2;
            const float2 bv = *(const float2*)(bias + col);
            *(float2*)(g_y + (size_t)row0 * 1024 + col) =
                make_float2(c[mt][nt][0] + bv.x, c[mt][nt][1] + bv.y);
            *(float2*)(g_y + (size_t)(row0 + 8) * 1024 + col) =
                make_float2(c[mt][nt][2] + bv.x, c[mt][nt][3] + bv.y);
        }
    }
}

// =============== 1024-pt radix-4 Stockham FFT (batched x4 per block) ===============
// 64 threads per FFT, 4 butterflies/thread/stage. SKW skew, arrays 1056 float2.
#define SKW(i) ((i) + ((i) >> 5))
#define FFT4_SMEM (2 * 4 * 1056 * (int)sizeof(float2))

__device__ __forceinline__ float2 cmul(float2 a, float2 b) {
    return make_float2(a.x * b.x - a.y * b.y, a.x * b.y + a.y * b.x);
}

// sA/sB: this FFT's buffers. st in [0,64). Result lands in sB.
__device__ __forceinline__ void fft1024_r4m(float2* sA, float2* sB, int st, float sign) {
    float2* src = sA;
    float2* dst = sB;
    int n = 1024;
    int logstr = 0;
#pragma unroll
    for (int stg = 0; stg < 5; stg++) {
        const int mq = n >> 2;
        const int str = 1 << logstr;
#pragma unroll
        for (int r = 0; r < 4; r++) {
            const int i = st + r * 64;
            const int p = i >> logstr;
            const int q = i & (str - 1);
            const int base = q + str * p;
            const int offc = str * mq;
            const float2 x0 = src[SKW(base)];
            const float2 x1 = src[SKW(base + offc)];
            const float2 x2 = src[SKW(base + 2 * offc)];
            const float2 x3 = src[SKW(base + 3 * offc)];
            const float2 a  = make_float2(x0.x + x2.x, x0.y + x2.y);
            const float2 b  = make_float2(x0.x - x2.x, x0.y - x2.y);
            const float2 cc = make_float2(x1.x + x3.x, x1.y + x3.y);
            const float2 dd = make_float2(x1.x - x3.x, x1.y - x3.y);
            const float2 idd = make_float2(-sign * dd.y, sign * dd.x);
            float sw, cw;
            sincospif(sign * 2.0f * (float)p / (float)n, &sw, &cw);
            const float2 w1 = make_float2(cw, sw);
            const float2 w2 = cmul(w1, w1);
            const float2 w3 = cmul(w1, w2);
            const int ob = q + str * 4 * p;
            dst[SKW(ob)]           = make_float2(a.x + cc.x, a.y + cc.y);
            dst[SKW(ob + str)]     = cmul(w1, make_float2(b.x + idd.x, b.y + idd.y));
            dst[SKW(ob + str * 2)] = cmul(w2, make_float2(a.x - cc.x, a.y - cc.y));
            dst[SKW(ob + str * 3)] = cmul(w3, make_float2(b.x - idd.x, b.y - idd.y));
        }
        __syncthreads();
        float2* tp = src; src = dst; dst = tp;
        n >>= 2;
        logstr += 2;
    }
}

// =============== forward rFFT (ortho), 4 channels per block ===============
// blk: b = blk>>7, c0 = (blk&127)*4 (4 consecutive channels, same head)
__global__ __launch_bounds__(256) void k_fft_fwd(const float* __restrict__ in, int mode) {
    extern __shared__ float2 fsm[];
    const int blk = blockIdx.x;
    const int b = blk >> 7, c0 = (blk & 127) * 4;
    const int tid = threadIdx.x;
    const int f = tid >> 6, st = tid & 63;
    float2* sA = fsm + f * 1056;
    float2* sB = fsm + (4 + f) * 1056;

    // coalesced-ish load: float4 across the 4 channels
    for (int l = tid; l < 1024; l += 256) {
        if (mode == 0) {
            const float* yr = g_y + ((size_t)(b * 1024 + l)) * 1024;
            const float4 a4 = *(const float4*)(yr + c0);
            const float4 g4 = *(const float4*)(yr + c0 + 512);
            const float va[4] = {a4.x, a4.y, a4.z, a4.w};
            const float vg[4] = {g4.x, g4.y, g4.z, g4.w};
#pragma unroll
            for (int j = 0; j < 4; j++)
                fsm[j * 1056 + SKW(l)] =
                    make_float2(va[j] * (1.0f / (1.0f + __expf(-vg[j]))), 0.f);
        } else {
            const float4 v4 = *(const float4*)(in + ((size_t)(b * 1024 + l)) * 512 + c0);
            const float vv[4] = {v4.x, v4.y, v4.z, v4.w};
#pragma unroll
            for (int j = 0; j < 4; j++)
                fsm[j * 1056 + SKW(l)] = make_float2(vv[j], 0.f);
        }
    }
    __syncthreads();
    fft1024_r4m(sA, sB, st, -1.0f);          // result in sB

    const int c = c0 + f;
    const int bh = b * 8 + (c >> 6), e = c & 63;
    const float sc = 1.0f / 32.0f;
    if (mode == 2) {
        __nv_bfloat16* vh = g_vsp_h + ((size_t)(bh * 64 + e)) * 1152;
        __nv_bfloat16* vl = g_vsp_l + ((size_t)(bh * 64 + e)) * 1152;
        for (int xx = st; xx < 576; xx += 64) {
            float re = 0.f, im = 0.f;
            if (xx < LF) { re = sB[SKW(xx)].x * sc; im = sB[SKW(xx)].y * sc; }
            __nv_bfloat16 h, l;
            split1(re, h, l); vh[xx] = h; vl[xx] = l;
            split1(im, h, l); vh[576 + xx] = h; vl[576 + xx] = l;
        }
    } else {
        const int width = (mode == 0) ? 640 : 576;
        __nv_bfloat16* base_h = (mode == 0) ? g_qsp_h : g_ksp_h;
        __nv_bfloat16* base_l = (mode == 0) ? g_qsp_l : g_ksp_l;
        __nv_bfloat16* rh = base_h + ((size_t)(bh * 128 + e)) * width;
        __nv_bfloat16* rl = base_l + ((size_t)(bh * 128 + e)) * width;
        __nv_bfloat16* ih = base_h + ((size_t)(bh * 128 + 64 + e)) * width;
        __nv_bfloat16* il = base_l + ((size_t)(bh * 128 + 64 + e)) * width;
        for (int xx = st; xx < width; xx += 64) {
            float re = 0.f, im = 0.f;
            if (xx < LF) { re = sB[SKW(xx)].x * sc; im = sB[SKW(xx)].y * sc; }
            __nv_bfloat16 h, l;
            split1(re, h, l); rh[xx] = h; rl[xx] = l;
            split1(im, h, l); ih[xx] = h; il[xx] = l;
        }
    }
}

// =============== frequency-domain attention on mma.sync (split bf16) ===============
#define AQH 0
#define AQL 34816
#define AKH 69632
#define AKL 88064
#define AVH 106496
#define AVL 123904
#define APH 141312
#define APL 176128
#define ADP 210944
#define ATTN_SMEM2 215040

__global__ void __launch_bounds__(256, 1) k_attn_mma() {
    extern __shared__ char smc[];
    const uint32_t sb = smem_u32(smc);
    const int tid = threadIdx.x, lane = tid & 31, wid = tid >> 5;
    const int bh = blockIdx.x, x0 = blockIdx.y * 128;
    const int wm = (wid & 3) * 32, wn = (wid >> 2) * 32, nwidx = wid >> 2;

    const int kTa = (lane & 7) + ((lane >> 4) & 1) * 8;
    const int mTa = ((lane >> 3) & 1) * 8;
    const int kTb = (lane & 7) + ((lane >> 3) & 1) * 8;
    const int nTb = ((lane >> 4) & 1) * 8;
    const int rA = (lane & 7) + (lane & 8);
    const int kA = ((lane >> 4) & 1) * 8;
    const int nB = (lane & 7) + ((lane >> 4) & 1) * 8;
    const int kB = ((lane >> 3) & 1) * 8;

    float sr[2][4][4], si_[2][4][4], orr[2][4][4], oii[2][4][4];
#pragma unroll
    for (int mt = 0; mt < 2; mt++)
#pragma unroll
        for (int t = 0; t < 4; t++)
#pragma unroll
            for (int r = 0; r < 4; r++) { orr[mt][t][r] = 0.f; oii[mt][t][r] = 0.f; }
    float dloc[2][2] = {{0.f, 0.f}, {0.f, 0.f}};

#pragma unroll
    for (int i = 0; i < 8; i++) {
        const int cc = tid + i * 256;
        const int row = cc >> 4, off = (cc & 15) * 16;
        const char* sh = (const char*)(g_qsp_h + ((size_t)(bh * 128 + row)) * 640 + x0) + off;
        const char* sl = (const char*)(g_qsp_l + ((size_t)(bh * 128 + row)) * 640 + x0) + off;
        CP16(sb + AQH + row * 272 + off, sh);
        CP16(sb + AQL + row * 272 + off, sl);
    }
    CP_COMMIT();

    for (int yt = 0; yt < 9; yt++) {
#pragma unroll
        for (int i = 0; i < 4; i++) {
            const int cc = tid + i * 256;
            const int row = cc >> 3, off = (cc & 7) * 16;
            const char* sh = (const char*)(g_ksp_h + ((size_t)(bh * 128 + row)) * 576 + yt * 64) + off;
            const char* sl = (const char*)(g_ksp_l + ((size_t)(bh * 128 + row)) * 576 + yt * 64) + off;
            CP16(sb + AKH + row * 144 + off, sh);
            CP16(sb + AKL + row * 144 + off, sl);
        }
#pragma unroll
        for (int i = 0; i < 4; i++) {
            const int cc = tid + i * 256;
            const int row = cc >> 4, seg = (cc >> 3) & 1, off = (cc & 7) * 16;
            const char* sh = (const char*)(g_vsp_h + ((size_t)(bh * 64 + row)) * 1152 + seg * 576 + yt * 64) + off;
            const char* sl = (const char*)(g_vsp_l + ((size_t)(bh * 64 + row)) * 1152 + seg * 576 + yt * 64) + off;
            CP16(sb + AVH + row * 272 + seg * 128 + off, sh);
            CP16(sb + AVL + row * 272 + seg * 128 + off, sl);
        }
        CP_COMMIT();
        CP_WAIT0();
        __syncthreads();

#pragma unroll
        for (int mt = 0; mt < 2; mt++)
#pragma unroll
            for (int t = 0; t < 4; t++)
#pragma unroll
                for (int r = 0; r < 4; r++) { sr[mt][t][r] = 0.f; si_[mt][t][r] = 0.f; }

        for (int p = 0; p < 4; p++) {
            const int c0 = p * 16, c1 = c0 + 64;
            uint32_t a0h[2][4], a0l[2][4], a1h[2][4], a1l[2][4];
#pragma unroll
            for (int mt = 0; mt < 2; mt++) {
                const uint32_t col = (wm + mt * 16 + mTa) * 2;
                uint32_t ad = sb + AQH + (c0 + kTa) * 272 + col;
                ldsm4t(a0h[mt], ad); ldsm4t(a0l[mt], ad + (AQL - AQH));
                ad = sb + AQH + (c1 + kTa) * 272 + col;
                ldsm4t(a1h[mt], ad); ldsm4t(a1l[mt], ad + (AQL - AQH));
            }
            uint32_t b0h[2][4], b0l[2][4], b1h[2][4], b1l[2][4];
#pragma unroll
            for (int np = 0; np < 2; np++) {
                const uint32_t col = (wn + np * 16 + nTb) * 2;
                uint32_t ad = sb + AKH + (c0 + kTb) * 144 + col;
                ldsm4t(b0h[np], ad); ldsm4t(b0l[np], ad + (AKL - AKH));
                ad = sb + AKH + (c1 + kTb) * 144 + col;
                ldsm4t(b1h[np], ad); ldsm4t(b1l[np], ad + (AKL - AKH));
            }
#pragma unroll
            for (int mt = 0; mt < 2; mt++)
#pragma unroll
                for (int np = 0; np < 2; np++)
#pragma unroll
                    for (int hf = 0; hf < 2; hf++) {
                        float* R = sr[mt][np * 2 + hf];
                        float* I = si_[mt][np * 2 + hf];
                        const uint32_t h0a = b0h[np][hf * 2], h0b = b0h[np][hf * 2 + 1];
                        const uint32_t l0a = b0l[np][hf * 2], l0b = b0l[np][hf * 2 + 1];
                        const uint32_t h1a = b1h[np][hf * 2], h1b = b1h[np][hf * 2 + 1];
                        const uint32_t l1a = b1l[np][hf * 2], l1b = b1l[np][hf * 2 + 1];
                        const uint32_t nh1a = h1a ^ SGN2, nh1b = h1b ^ SGN2;
                        const uint32_t nl1a = l1a ^ SGN2, nl1b = l1b ^ SGN2;
                        mma_bf16(R, a0h[mt], h0a, h0b);
                        mma_bf16(R, a0h[mt], l0a, l0b);
                        mma_bf16(R, a0l[mt], h0a, h0b);
                        mma_bf16(R, a1h[mt], h1a, h1b);
                        mma_bf16(R, a1h[mt], l1a, l1b);
                        mma_bf16(R, a1l[mt], h1a, h1b);
                        mma_bf16(I, a1h[mt], h0a, h0b);
                        mma_bf16(I, a1h[mt], l0a, l0b);
                        mma_bf16(I, a1l[mt], h0a, h0b);
                        mma_bf16(I, a0h[mt], nh1a, nh1b);
                        mma_bf16(I, a0h[mt], nl1a, nl1b);
                        mma_bf16(I, a0l[mt], nh1a, nh1b);
                    }
        }

#pragma unroll
        for (int mt = 0; mt < 2; mt++)
#pragma unroll
            for (int np = 0; np < 2; np++)
#pragma unroll
                for (int hf = 0; hf < 2; hf++) {
                    float* R = sr[mt][np * 2 + hf];
                    float* I = si_[mt][np * 2 + hf];
                    const int ycol = wn + np * 16 + hf * 8 + (lane & 3) * 2;
#pragma unroll
                    for (int jh = 0; jh < 2; jh++) {
                        const int row = wm + mt * 16 + (lane >> 2) + jh * 8;
                        const float re0 = R[jh * 2] * 0.125f, im0 = I[jh * 2] * 0.125f;
                        const float re1 = R[jh * 2 + 1] * 0.125f, im1 = I[jh * 2 + 1] * 0.125f;
                        const float m0 = __fsqrt_rn(re0 * re0 + im0 * im0);
                        const float m1 = __fsqrt_rn(re1 * re1 + im1 * im1);
                        const float w0 = 1.0f + 1.0f / (1.0f + __expf(-m0));
                        const float w1 = 1.0f + 1.0f / (1.0f + __expf(-m1));
                        dloc[mt][jh] += m0 * w0 + m1 * w1;
                        const float pr0 = re0 * w0, pr1 = re1 * w1;
                        const float pi0 = im0 * w0, pi1 = im1 * w1;
                        __nv_bfloat16 h0, l0, h1, l1;
                        split1(pr0, h0, l0); split1(pr1, h1, l1);
                        __nv_bfloat162 hp = {h0, h1}, lp = {l0, l1};
                        *(uint32_t*)(smc + APH + row * 272 + ycol * 2) = *(uint32_t*)&hp;
                        *(uint32_t*)(smc + APL + row * 272 + ycol * 2) = *(uint32_t*)&lp;
                        split1(pi0, h0, l0); split1(pi1, h1, l1);
                        __nv_bfloat162 hp2 = {h0, h1}, lp2 = {l0, l1};
                        *(uint32_t*)(smc + APH + row * 272 + 128 + ycol * 2) = *(uint32_t*)&hp2;
                        *(uint32_t*)(smc + APL + row * 272 + 128 + ycol * 2) = *(uint32_t*)&lp2;
                    }
                }
        __syncthreads();

        for (int p = 0; p < 4; p++) {
            const int c0 = p * 16, c1 = c0 + 64;
            uint32_t a0h[2][4], a0l[2][4], a1h[2][4], a1l[2][4];
#pragma unroll
            for (int mt = 0; mt < 2; mt++) {
                const uint32_t rowb = sb + APH + (wm + mt * 16 + rA) * 272;
                uint32_t ad = rowb + (c0 + kA) * 2;
                ldsm4(a0h[mt], ad); ldsm4(a0l[mt], ad + (APL - APH));
                ad = rowb + (c1 + kA) * 2;
                ldsm4(a1h[mt], ad); ldsm4(a1l[mt], ad + (APL - APH));
            }
            uint32_t b0h[2][4], b0l[2][4], b1h[2][4], b1l[2][4];
#pragma unroll
            for (int np = 0; np < 2; np++) {
                const uint32_t rowb = sb + AVH + (wn + np * 16 + nB) * 272;
                uint32_t ad = rowb + (c0 + kB) * 2;
                ldsm4(b0h[np], ad); ldsm4(b0l[np], ad + (AVL - AVH));
                ad = rowb + (c1 + kB) * 2;
                ldsm4(b1h[np], ad); ldsm4(b1l[np], ad + (AVL - AVH));
            }
#pragma unroll
            for (int mt = 0; mt < 2; mt++)
#pragma unroll
                for (int np = 0; np < 2; np++)
#pragma unroll
                    for (int hf = 0; hf < 2; hf++) {
                        float* Or = orr[mt][np * 2 + hf];
                        float* Oi = oii[mt][np * 2 + hf];
                        const uint32_t h0a = b0h[np][hf * 2], h0b = b0h[np][hf * 2 + 1];
                        const uint32_t l0a = b0l[np][hf * 2], l0b = b0l[np][hf * 2 + 1];
                        const uint32_t h1a = b1h[np][hf * 2], h1b = b1h[np][hf * 2 + 1];
                        const uint32_t l1a = b1l[np][hf * 2], l1b = b1l[np][hf * 2 + 1];
                        const uint32_t nh1a = h1a ^ SGN2, nh1b = h1b ^ SGN2;
                        const uint32_t nl1a = l1a ^ SGN2, nl1b = l1b ^ SGN2;
                        mma_bf16(Or, a0h[mt], h0a, h0b);
                        mma_bf16(Or, a0h[mt], l0a, l0b);
                        mma_bf16(Or, a0l[mt], h0a, h0b);
                        mma_bf16(Or, a1h[mt], nh1a, nh1b);
                        mma_bf16(Or, a1h[mt], nl1a, nl1b);
                        mma_bf16(Or, a1l[mt], nh1a, nh1b);
                        mma_bf16(Oi, a0h[mt], h1a, h1b);
                        mma_bf16(Oi, a0h[mt], l1a, l1b);
                        mma_bf16(Oi, a0l[mt], h1a, h1b);
                        mma_bf16(Oi, a1h[mt], h0a, h0b);
                        mma_bf16(Oi, a1h[mt], l0a, l0b);
                        mma_bf16(Oi, a1l[mt], h0a, h0b);
                    }
        }
        __syncthreads();
    }

    float* dp = (float*)(smc + ADP);
#pragma unroll
    for (int mt = 0; mt < 2; mt++)
#pragma unroll
        for (int jh = 0; jh < 2; jh++) {
            const int row = wm + mt * 16 + (lane >> 2) + jh * 8;
            dp[row * 8 + nwidx * 4 + (lane & 3)] = dloc[mt][jh];
        }
    __syncthreads();

#pragma unroll
    for (int mt = 0; mt < 2; mt++)
#pragma unroll
        for (int jh = 0; jh < 2; jh++) {
            const int row = wm + mt * 16 + (lane >> 2) + jh * 8;
            const int x = x0 + row;
            if (x >= LF) continue;
            float dn = 0.f;
#pragma unroll
            for (int t = 0; t < 8; t++) dn += dp[row * 8 + t];
            const float inv = 1.0f / fmaxf(dn, 1e-12f);
#pragma unroll
            for (int np = 0; np < 2; np++)
#pragma unroll
                for (int hf = 0; hf < 2; hf++) {
                    const int e0 = wn + np * 16 + hf * 8 + (lane & 3) * 2;
                    const float* Or = orr[mt][np * 2 + hf];
                    const float* Oi = oii[mt][np * 2 + hf];
                    const int j0 = jh * 2, j1 = jh * 2 + 1;
                    float4 v = make_float4(Or[j0] * inv, Oi[j0] * inv,
                                           Or[j1] * inv, Oi[j1] * inv);
                    *(float4*)(g_of + ((size_t)(bh * LF + x)) * 64 + e0) = v;
                }
        }
}

// =============== inverse: Hermitian extension + iFFT (ortho), 4 e per block ===============
// blk: bh = blk>>4, e0 = (blk&15)*4
__global__ __launch_bounds__(256) void k_fft_inv(float* __restrict__ out) {
    extern __shared__ float2 fsm[];
    const int blk = blockIdx.x;
    const int bh = blk >> 4, e0 = (blk & 15) * 4;
    const int tid = threadIdx.x;
    const int f = tid >> 6, st = tid & 63;
    float2* sA = fsm + f * 1056;
    float2* sB = fsm + (4 + f) * 1056;
    const float2* ip = g_of + (size_t)bh * LF * 64 + e0;

    for (int xx = tid; xx < 1024; xx += 256) {
        const int src = (xx <= 512) ? xx : (1024 - xx);
        const float sgn = (xx <= 512) ? 1.f : -1.f;
        const float4 v0 = *(const float4*)(ip + (size_t)src * 64);      // e0, e0+1
        const float4 v1 = *(const float4*)(ip + (size_t)src * 64 + 2);  // e0+2, e0+3
        fsm[0 * 1056 + SKW(xx)] = make_float2(v0.x, sgn * v0.y);
        fsm[1 * 1056 + SKW(xx)] = make_float2(v0.z, sgn * v0.w);
        fsm[2 * 1056 + SKW(xx)] = make_float2(v1.x, sgn * v1.y);
        fsm[3 * 1056 + SKW(xx)] = make_float2(v1.z, sgn * v1.w);
    }
    __syncthreads();
    fft1024_r4m(sA, sB, st, +1.0f);          // result in sB

    const int b = bh >> 3, h = bh & 7;
    float* op = out + (size_t)b * 1024 * 512 + h * 64 + e0;
    const float sc = 1.0f / 32.0f;
    for (int l = tid; l < 1024; l += 256) {
        const float4 o4 = make_float4(fsm[(4 + 0) * 1056 + SKW(l)].x * sc,
                                      fsm[(4 + 1) * 1056 + SKW(l)].x * sc,
                                      fsm[(4 + 2) * 1056 + SKW(l)].x * sc,
                                      fsm[(4 + 3) * 1056 + SKW(l)].x * sc);
        *(float4*)(op + (size_t)l * 512) = o4;
    }
}

// ============================ launch ============================
extern "C" void kernel_launch(void* const* d_in, const int* in_sizes, int n_in,
                              void* d_out, int out_size) {
    const float* q    = (const float*)d_in[0];
    const float* k    = (const float*)d_in[1];
    const float* v    = (const float*)d_in[2];
    const float* W    = (const float*)d_in[3];
    const float* bias = (const float*)d_in[4];
    float* out = (float*)d_out;

    cudaFuncSetAttribute(k_conv_mma, cudaFuncAttributeMaxDynamicSharedMemorySize,
                         (int)CONV_SMEM);
    cudaFuncSetAttribute(k_attn_mma, cudaFuncAttributeMaxDynamicSharedMemorySize,
                         (int)ATTN_SMEM2);
    cudaFuncSetAttribute(k_fft_fwd, cudaFuncAttributeMaxDynamicSharedMemorySize,
                         (int)FFT4_SMEM);
    cudaFuncSetAttribute(k_fft_inv, cudaFuncAttributeMaxDynamicSharedMemorySize,
                         (int)FFT4_SMEM);

    k_split_x<<<16384, 256>>>(q);
    k_transpose_w<<<(1024 * 512 * 3 + 255) / 256, 256>>>(W);
    k_conv_mma<<<dim3(8, 128), 256, CONV_SMEM>>>(q, bias);
    k_fft_fwd<<<2048, 256, FFT4_SMEM>>>(nullptr, 0);   // q2 (GLU of conv output)
    k_fft_fwd<<<2048, 256, FFT4_SMEM>>>(k, 1);
    k_fft_fwd<<<2048, 256, FFT4_SMEM>>>(v, 2);
    k_attn_mma<<<dim3(128, 5), 256, ATTN_SMEM2>>>();
    k_fft_inv<<<2048, 256, FFT4_SMEM>>>(out);
}